// round 7
// baseline (speedup 1.0000x reference)
#include <cuda_runtime.h>

// ---------------- problem constants ----------------
#define NB   128            // batch
#define L    256            // seq len (both sentences)
#define EMB  512
#define HID  1024
#define TOK  (NB * L)       // 32768 tokens per sentence

// ---------------- scratch (device globals; no allocations) ----------------
__device__ float g_bufA[TOK * HID];     // f1, later concat input
__device__ float g_bufB[TOK * HID];     // f2, later cmp output
__device__ float g_bufH[TOK * HID];     // hidden scratch
__device__ float g_e   [NB * L * L];    // logits e1
__device__ float g_w1  [NB * L * L];    // row softmax   [B, L1, L2]
__device__ float g_w2  [NB * L * L];    // col softmax   [B, L2, L1]
__device__ float g_att1[NB * L * EMB];
__device__ float g_att2[NB * L * EMB];
__device__ float g_s   [NB * 2 * HID];  // [s1 | s2]
__device__ float g_agg1[NB * HID];
__device__ float g_agg2[NB * HID];

// ---------------- generic tiled fp32 GEMM ----------------
// C = act(A @ op(B) + bias)
//   BT=true : B is [N,K] row-major (C = A @ B^T)   -- weight layout
//   BT=false: B is [K,N] row-major (C = A @ B)
// Tiles: 128x128x16, 256 threads, 8x8 per thread. All dims assumed to divide
// evenly (true for every call in this problem).
template<bool BT, bool BIAS, bool RELU>
__global__ void __launch_bounds__(256)
gemm_kernel(const float* __restrict__ A, const float* __restrict__ B,
            const float* __restrict__ bias, float* __restrict__ C,
            int N, int K,
            long sA, long sB, long sC)
{
    constexpr int BM = 128, BN = 128, BK = 16;
    __shared__ __align__(16) float As[BK][BM];
    __shared__ __align__(16) float Bs[BK][BN];

    const int bx = blockIdx.x, by = blockIdx.y, bz = blockIdx.z;
    const int tid = threadIdx.x;
    const int tx = tid & 15;        // 0..15 -> 8 output cols each
    const int ty = tid >> 4;        // 0..15 -> 8 output rows each

    A += bz * sA + (long)by * BM * K;
    if (BT) B += bz * sB + (long)bx * BN * K;
    else    B += bz * sB + bx * BN;
    C += bz * sC + (long)by * BM * N + bx * BN;

    float acc[8][8];
#pragma unroll
    for (int i = 0; i < 8; i++)
#pragma unroll
        for (int j = 0; j < 8; j++) acc[i][j] = 0.f;

    for (int k0 = 0; k0 < K; k0 += BK) {
        // --- load A tile [BM x BK], store transposed As[k][m] ---
#pragma unroll
        for (int it = 0; it < 2; it++) {
            int id = it * 256 + tid;          // 512 float4 slots
            int r  = id >> 2;                 // row in tile (0..127)
            int c4 = (id & 3) << 2;           // k offset (0,4,8,12)
            float4 v = *(const float4*)(A + (long)r * K + k0 + c4);
            As[c4 + 0][r] = v.x; As[c4 + 1][r] = v.y;
            As[c4 + 2][r] = v.z; As[c4 + 3][r] = v.w;
        }
        // --- load B tile ---
        if (BT) {
#pragma unroll
            for (int it = 0; it < 2; it++) {
                int id = it * 256 + tid;
                int r  = id >> 2;             // n in tile
                int c4 = (id & 3) << 2;       // k offset
                float4 v = *(const float4*)(B + (long)r * K + k0 + c4);
                Bs[c4 + 0][r] = v.x; Bs[c4 + 1][r] = v.y;
                Bs[c4 + 2][r] = v.z; Bs[c4 + 3][r] = v.w;
            }
        } else {
#pragma unroll
            for (int it = 0; it < 2; it++) {
                int id = it * 256 + tid;
                int r  = id >> 5;             // k row (0..15)
                int c  = (id & 31) << 2;      // n offset
                float4 v = *(const float4*)(B + (long)(k0 + r) * N + c);
                *(float4*)&Bs[r][c] = v;
            }
        }
        __syncthreads();

#pragma unroll
        for (int kk = 0; kk < BK; kk++) {
            float a[8], b[8];
            *(float4*)&a[0] = *(float4*)&As[kk][ty * 8];
            *(float4*)&a[4] = *(float4*)&As[kk][ty * 8 + 4];
            *(float4*)&b[0] = *(float4*)&Bs[kk][tx * 8];
            *(float4*)&b[4] = *(float4*)&Bs[kk][tx * 8 + 4];
#pragma unroll
            for (int i = 0; i < 8; i++)
#pragma unroll
                for (int j = 0; j < 8; j++)
                    acc[i][j] += a[i] * b[j];
        }
        __syncthreads();
    }

    // --- epilogue: bias + relu + store ---
    float bv[8];
    if (BIAS) {
        *(float4*)&bv[0] = *(const float4*)(bias + bx * BN + tx * 8);
        *(float4*)&bv[4] = *(const float4*)(bias + bx * BN + tx * 8 + 4);
    }
#pragma unroll
    for (int i = 0; i < 8; i++) {
        int m = ty * 8 + i;
#pragma unroll
        for (int jj = 0; jj < 2; jj++) {
            float4 v;
            float* p = &acc[i][jj * 4];
            v.x = p[0]; v.y = p[1]; v.z = p[2]; v.w = p[3];
            if (BIAS) {
                v.x += bv[jj * 4 + 0]; v.y += bv[jj * 4 + 1];
                v.z += bv[jj * 4 + 2]; v.w += bv[jj * 4 + 3];
            }
            if (RELU) {
                v.x = fmaxf(v.x, 0.f); v.y = fmaxf(v.y, 0.f);
                v.z = fmaxf(v.z, 0.f); v.w = fmaxf(v.w, 0.f);
            }
            *(float4*)(C + (long)m * N + tx * 8 + jj * 4) = v;
        }
    }
}

// ---------------- softmax over rows (axis j of e1[b,i,j]) ----------------
__global__ void softmax_rows_kernel(const float* __restrict__ e,
                                    float* __restrict__ w)
{
    long row = blockIdx.x;               // b*L + i
    int t = threadIdx.x;                 // j (256 threads)
    float v = e[row * L + t];

    __shared__ float sm[8];
    // block max
    float m = v;
#pragma unroll
    for (int s = 16; s; s >>= 1) m = fmaxf(m, __shfl_xor_sync(~0u, m, s));
    if ((t & 31) == 0) sm[t >> 5] = m;
    __syncthreads();
    m = sm[0];
#pragma unroll
    for (int k = 1; k < 8; k++) m = fmaxf(m, sm[k]);
    __syncthreads();

    float ex = __expf(v - m);
    float s = ex;
#pragma unroll
    for (int sh = 16; sh; sh >>= 1) s += __shfl_xor_sync(~0u, s, sh);
    if ((t & 31) == 0) sm[t >> 5] = s;
    __syncthreads();
    s = sm[0];
#pragma unroll
    for (int k = 1; k < 8; k++) s += sm[k];

    w[row * L + t] = ex * (1.f / s);
}

// ---------------- softmax over columns: w2[b,j,i] = softmax_i e[b,i,j] -----
__global__ void softmax_cols_kernel(const float* __restrict__ e,
                                    float* __restrict__ w2)
{
    int b  = blockIdx.x;
    int j0 = blockIdx.y * 32;
    int tx = threadIdx.x & 31;           // column within 32-wide tile
    int ty = threadIdx.x >> 5;           // 0..7 (row group)

    const float* eb = e + (long)b * L * L;
    float vals[32];
    float m = -1e30f;
#pragma unroll
    for (int r = 0; r < 32; r++) {
        float v = eb[(long)(ty + 8 * r) * L + j0 + tx];
        vals[r] = v;
        m = fmaxf(m, v);
    }
    __shared__ float red[8][33];
    red[ty][tx] = m;
    __syncthreads();
    if (ty == 0) {
        float mm = red[0][tx];
#pragma unroll
        for (int t = 1; t < 8; t++) mm = fmaxf(mm, red[t][tx]);
        red[0][tx] = mm;
    }
    __syncthreads();
    m = red[0][tx];
    __syncthreads();

    float s = 0.f;
#pragma unroll
    for (int r = 0; r < 32; r++) { vals[r] = __expf(vals[r] - m); s += vals[r]; }
    red[ty][tx] = s;
    __syncthreads();
    if (ty == 0) {
        float ss = red[0][tx];
#pragma unroll
        for (int t = 1; t < 8; t++) ss += red[t][tx];
        red[0][tx] = ss;
    }
    __syncthreads();
    float inv = 1.f / red[0][tx];

    float* wb = w2 + (long)b * L * L;
#pragma unroll
    for (int r = 0; r < 32; r++)
        wb[(long)(j0 + tx) * L + (ty + 8 * r)] = vals[r] * inv;
}

// ---------------- tokenwise concat [att | sent] (512 + 512 -> 1024) --------
__global__ void concat_kernel(const float* __restrict__ att,
                              const float* __restrict__ sent,
                              float* __restrict__ out)
{
    long row = blockIdx.x;               // token
    int c4 = threadIdx.x * 4;            // 256 threads * 4 floats = 1024 cols
    const float* src = (c4 < EMB) ? (att  + row * EMB + c4)
                                  : (sent + row * EMB + (c4 - EMB));
    *(float4*)(out + row * (2 * EMB) + c4) = *(const float4*)src;
}

// ---------------- column sum over seq: s[b,h] = sum_i cmp[b,i,h] -----------
__global__ void colsum_kernel(const float* __restrict__ cmp,
                              float* __restrict__ s, int offset)
{
    int b = blockIdx.x;
    int h = blockIdx.y * 256 + threadIdx.x;
    const float* p = cmp + (long)b * L * HID + h;
    float acc = 0.f;
#pragma unroll 4
    for (int i = 0; i < L; i++) acc += p[(long)i * HID];
    s[(long)b * (2 * HID) + offset + h] = acc;
}

// ---------------- final linear: out[b,o] = agg2[b,:] . fin_w[o,:] + b ------
__global__ void final_kernel(const float* __restrict__ h,
                             const float* __restrict__ w,
                             const float* __restrict__ bias,
                             float* __restrict__ out)
{
    int b = blockIdx.x;
    int o = threadIdx.x >> 5;            // 3 warps
    int lane = threadIdx.x & 31;
    float acc = 0.f;
    for (int k = lane; k < HID; k += 32)
        acc += h[(long)b * HID + k] * w[(long)o * HID + k];
#pragma unroll
    for (int s = 16; s; s >>= 1) acc += __shfl_xor_sync(~0u, acc, s);
    if (lane == 0) out[b * 3 + o] = acc + bias[o];
}

// ---------------- host ----------------
static float* symaddr(const void* sym)
{
    void* p = nullptr;
    cudaGetSymbolAddress(&p, sym);
    return (float*)p;
}

extern "C" void kernel_launch(void* const* d_in, const int* in_sizes, int n_in,
                              void* d_out, int out_size)
{
    (void)in_sizes; (void)n_in; (void)out_size;

    const float* sent1 = (const float*)d_in[0];
    const float* sent2 = (const float*)d_in[1];
    const float* f_w1  = (const float*)d_in[2];
    const float* f_b1  = (const float*)d_in[3];
    const float* f_w2  = (const float*)d_in[4];
    const float* f_b2  = (const float*)d_in[5];
    const float* gw1   = (const float*)d_in[6];
    const float* gb1   = (const float*)d_in[7];
    const float* gw2   = (const float*)d_in[8];
    const float* gb2   = (const float*)d_in[9];
    const float* hw1   = (const float*)d_in[10];
    const float* hb1   = (const float*)d_in[11];
    const float* hw2   = (const float*)d_in[12];
    const float* hb2   = (const float*)d_in[13];
    const float* finw  = (const float*)d_in[14];
    const float* finb  = (const float*)d_in[15];
    float* out = (float*)d_out;

    float* bufA = symaddr(g_bufA);
    float* bufB = symaddr(g_bufB);
    float* bufH = symaddr(g_bufH);
    float* e    = symaddr(g_e);
    float* w1a  = symaddr(g_w1);
    float* w2a  = symaddr(g_w2);
    float* att1 = symaddr(g_att1);
    float* att2 = symaddr(g_att2);
    float* sbuf = symaddr(g_s);
    float* agg1 = symaddr(g_agg1);
    float* agg2 = symaddr(g_agg2);

    // helper: C = relu(A @ W^T + b),  A:[M,K], W:[N,K]
    auto mlp = [](const float* A, const float* W, const float* b, float* C,
                  int M, int N, int K) {
        dim3 grid(N / 128, M / 128, 1);
        gemm_kernel<true, true, true><<<grid, 256>>>(A, W, b, C, N, K, 0, 0, 0);
    };

    // ---- Attend: f MLP on both sentences ----
    mlp(sent1, f_w1, f_b1, bufH, TOK, HID, EMB);
    mlp(bufH,  f_w2, f_b2, bufA, TOK, HID, HID);   // f1
    mlp(sent2, f_w1, f_b1, bufH, TOK, HID, EMB);
    mlp(bufH,  f_w2, f_b2, bufB, TOK, HID, HID);   // f2

    // e1[b] = f1[b] @ f2[b]^T   (batched NT, 256x256x1024)
    {
        dim3 grid(L / 128, L / 128, NB);
        gemm_kernel<true, false, false><<<grid, 256>>>(
            bufA, bufB, nullptr, e, L, HID,
            (long)L * HID, (long)L * HID, (long)L * L);
    }

    softmax_rows_kernel<<<NB * L, 256>>>(e, w1a);
    softmax_cols_kernel<<<dim3(NB, L / 32), 256>>>(e, w2a);

    // att1[b] = w1a[b] @ sent2[b]   (batched NN, 256x512x256)
    // att2[b] = w2a[b] @ sent1[b]
    {
        dim3 grid(EMB / 128, L / 128, NB);
        gemm_kernel<false, false, false><<<grid, 256>>>(
            w1a, sent2, nullptr, att1, EMB, L,
            (long)L * L, (long)L * EMB, (long)L * EMB);
        gemm_kernel<false, false, false><<<grid, 256>>>(
            w2a, sent1, nullptr, att2, EMB, L,
            (long)L * L, (long)L * EMB, (long)L * EMB);
    }

    // ---- Compare + aggregate-sum, sentence 1 ----
    concat_kernel<<<TOK, 256>>>(att1, sent1, bufA);
    mlp(bufA, gw1, gb1, bufH, TOK, HID, 2 * EMB);
    mlp(bufH, gw2, gb2, bufB, TOK, HID, HID);
    colsum_kernel<<<dim3(NB, HID / 256), 256>>>(bufB, sbuf, 0);

    // ---- Compare + aggregate-sum, sentence 2 ----
    concat_kernel<<<TOK, 256>>>(att2, sent2, bufA);
    mlp(bufA, gw1, gb1, bufH, TOK, HID, 2 * EMB);
    mlp(bufH, gw2, gb2, bufB, TOK, HID, HID);
    colsum_kernel<<<dim3(NB, HID / 256), 256>>>(bufB, sbuf, HID);

    // ---- Aggregate MLP + final linear ----
    mlp(sbuf, hw1, hb1, agg1, NB, HID, 2 * HID);
    mlp(agg1, hw2, hb2, agg2, NB, HID, HID);
    final_kernel<<<NB, 96>>>(agg2, finw, finb, out);
}

// round 9
// speedup vs baseline: 2.1308x; 2.1308x over previous
#include <cuda_runtime.h>

// ---------------- problem constants ----------------
#define NB   128            // batch
#define L    256            // seq len (both sentences)
#define EMB  512
#define HID  1024
#define TOK  (NB * L)       // 32768 tokens per sentence

// ---------------- scratch (device globals; no allocations) ----------------
__device__ __align__(16) float g_f1  [TOK * HID];
__device__ __align__(16) float g_f2  [TOK * HID];
__device__ __align__(16) float g_bufH[TOK * HID];
__device__ __align__(16) float g_bufB[TOK * HID];
__device__ __align__(16) float g_e   [NB * L * L];
__device__ __align__(16) float g_w1  [NB * L * L];   // row softmax [B,L1,L2]
__device__ __align__(16) float g_w2  [NB * L * L];   // col softmax [B,L2,L1]
__device__ __align__(16) float g_att1[NB * L * EMB];
__device__ __align__(16) float g_att2[NB * L * EMB];
__device__ __align__(16) float g_s   [NB * 2 * HID]; // [s1 | s2]
__device__ __align__(16) float g_agg1[NB * HID];
__device__ __align__(16) float g_agg2[NB * HID];

// ---------------- tf32 helpers ----------------
__device__ __forceinline__ unsigned f2t(float x)
{
    unsigned u;
    asm("cvt.rna.tf32.f32 %0, %1;" : "=r"(u) : "f"(x));
    return u;
}

__device__ __forceinline__ void mma_tf32(float* c, const unsigned* a, const unsigned* b)
{
    asm volatile(
        "mma.sync.aligned.m16n8k8.row.col.f32.tf32.tf32.f32 "
        "{%0,%1,%2,%3},{%4,%5,%6,%7},{%8,%9},{%0,%1,%2,%3};"
        : "+f"(c[0]), "+f"(c[1]), "+f"(c[2]), "+f"(c[3])
        : "r"(a[0]), "r"(a[1]), "r"(a[2]), "r"(a[3]), "r"(b[0]), "r"(b[1]));
}

// ---------------- tf32 tensor-core GEMM ----------------
// C = act(A @ op(B) + bias)
//   BT=true : B is [N,K] row-major (C = A @ B^T)   -- weight layout
//   BT=false: B is [K,N] row-major (C = A @ B)
//   SPLIT   : A is concat(A[:,0:512] , A2[:,0:512]) along K (compare MLP)
// Block tile 128x128x16, 8 warps (2x4), warp tile 64x32, m16n8k8 tf32 mma.
// Shared tiles stored in fragment-native layout: per 16x8 (A) / 8x8 (B)
// mma tile, lane-l's registers are contiguous -> LDS.128 / LDS.64 per frag,
// conflict-free. Double-buffered (2 stages) with register staging + RNA cvt.
template<bool BT, bool BIAS, bool RELU, bool SPLIT>
__global__ void __launch_bounds__(256, 2)
mma_gemm(const float* __restrict__ A, const float* __restrict__ A2,
         const float* __restrict__ B, const float* __restrict__ bias,
         float* __restrict__ C, int N, int K,
         long sA, long sB, long sC)
{
    __shared__ __align__(16) unsigned As[2][2048];   // 2 x 8KB
    __shared__ __align__(16) unsigned Bs[2][2048];   // 2 x 8KB

    const int tid  = threadIdx.x;
    const int lane = tid & 31;
    const int warp = tid >> 5;
    const int wm   = warp >> 2;      // 0..1
    const int wn   = warp & 3;       // 0..3
    const int bx = blockIdx.x, by = blockIdx.y, bz = blockIdx.z;

    const float* Ab;
    const float* A2b = nullptr;
    if (SPLIT) {
        Ab  = A  + (long)by * 128 * EMB;
        A2b = A2 + (long)by * 128 * EMB;
    } else {
        Ab = A + bz * sA + (long)by * 128 * (long)K;
    }
    const float* Bb = BT ? B + bz * sB + (long)bx * 128 * (long)K
                         : B + bz * sB + bx * 128;
    float* Cb = C + bz * sC + (long)by * 128 * (long)N + bx * 128;

    // ---- per-thread global-load / shared-store geometry (constant) ----
    int rA[2], cA[2], stA[2];
    int rB[2], cB[2], stB[2];
#pragma unroll
    for (int it = 0; it < 2; it++) {
        int id = it * 256 + tid;
        {   // A: tile 128 rows x 16 cols, float4 per slot
            int r = id >> 2, c4 = (id & 3) << 2;
            rA[it] = r; cA[it] = c4;
            int kt = c4 >> 3, cb = c4 & 7, mt = r >> 4, rr = r & 15;
            // frag idx = (rr>=8) + 2*(cc>=4); element e adds +4 (lane+e)
            stA[it] = ((kt * 8 + mt) * 32 + (rr & 7) * 4) * 4
                      + ((rr >> 3) & 1) + (cb ? 2 : 0);
        }
        if (BT) {   // B: [N,K] tile 128 n-rows x 16 k-cols
            int n = id >> 2, c4 = (id & 3) << 2;
            rB[it] = n; cB[it] = c4;
            int kt = c4 >> 3, kb = c4 & 7, nt = n >> 3, nn = n & 7;
            stB[it] = ((kt * 16 + nt) * 32 + nn * 4) * 2 + (kb ? 1 : 0); // +2e
        } else {    // B: [K,N] tile 16 k-rows x 128 n-cols
            int k = id >> 5, n4 = (id & 31) << 2;
            rB[it] = k; cB[it] = n4;
            int kt = k >> 3, kk = k & 7, nt = n4 >> 3, nb = n4 & 7;
            stB[it] = ((kt * 16 + nt) * 32 + nb * 4 + (kk & 3)) * 2
                      + (kk >= 4 ? 1 : 0);                               // +8e
        }
    }

    float4 vA[2], vB[2];

    auto load_tile = [&](int k0) {
#pragma unroll
        for (int it = 0; it < 2; it++) {
            if (SPLIT) {
                int c = k0 + cA[it];
                const float* p = (c < EMB) ? (Ab  + (long)rA[it] * EMB + c)
                                           : (A2b + (long)rA[it] * EMB + (c - EMB));
                vA[it] = *(const float4*)p;
            } else {
                vA[it] = *(const float4*)(Ab + (long)rA[it] * K + k0 + cA[it]);
            }
            if (BT)
                vB[it] = *(const float4*)(Bb + (long)rB[it] * K + k0 + cB[it]);
            else
                vB[it] = *(const float4*)(Bb + (long)(k0 + rB[it]) * N + cB[it]);
        }
    };

    auto store_tile = [&](int s) {
#pragma unroll
        for (int it = 0; it < 2; it++) {
            unsigned* pa = &As[s][stA[it]];
            pa[0]  = f2t(vA[it].x);
            pa[4]  = f2t(vA[it].y);
            pa[8]  = f2t(vA[it].z);
            pa[12] = f2t(vA[it].w);
            unsigned* pb = &Bs[s][stB[it]];
            if (BT) {
                pb[0] = f2t(vB[it].x); pb[2] = f2t(vB[it].y);
                pb[4] = f2t(vB[it].z); pb[6] = f2t(vB[it].w);
            } else {
                pb[0]  = f2t(vB[it].x); pb[8]  = f2t(vB[it].y);
                pb[16] = f2t(vB[it].z); pb[24] = f2t(vB[it].w);
            }
        }
    };

    float acc[4][4][4];
#pragma unroll
    for (int i = 0; i < 4; i++)
#pragma unroll
        for (int j = 0; j < 4; j++)
#pragma unroll
            for (int q = 0; q < 4; q++) acc[i][j][q] = 0.f;

    auto compute = [&](int s) {
#pragma unroll
        for (int kt = 0; kt < 2; kt++) {
            unsigned a[4][4], b[4][2];
#pragma unroll
            for (int i = 0; i < 4; i++) {
                int mt = wm * 4 + i;
                *(uint4*)a[i] = *(const uint4*)&As[s][((kt * 8 + mt) * 32 + lane) * 4];
            }
#pragma unroll
            for (int j = 0; j < 4; j++) {
                int nt = wn * 4 + j;
                *(uint2*)b[j] = *(const uint2*)&Bs[s][((kt * 16 + nt) * 32 + lane) * 2];
            }
#pragma unroll
            for (int i = 0; i < 4; i++)
#pragma unroll
                for (int j = 0; j < 4; j++)
                    mma_tf32(acc[i][j], a[i], b[j]);
        }
    };

    const int nK = K >> 4;
    load_tile(0);
    store_tile(0);
    __syncthreads();
    int s = 0;
    for (int kb = 0; kb < nK; kb++) {
        if (kb + 1 < nK) load_tile((kb + 1) << 4);   // LDG in flight over mma
        compute(s);
        if (kb + 1 < nK) {
            store_tile(s ^ 1);                        // other buffer: no hazard
            __syncthreads();
            s ^= 1;
        }
    }

    // ---- epilogue: bias + relu + float2 stores ----
    const int g = lane >> 2, t = lane & 3;
#pragma unroll
    for (int j = 0; j < 4; j++) {
        int col = wn * 32 + j * 8 + t * 2;
        float2 bb = make_float2(0.f, 0.f);
        if (BIAS) bb = *(const float2*)(bias + bx * 128 + col);
#pragma unroll
        for (int i = 0; i < 4; i++) {
            int row = wm * 64 + i * 16 + g;
            float2 v0 = make_float2(acc[i][j][0] + bb.x, acc[i][j][1] + bb.y);
            float2 v1 = make_float2(acc[i][j][2] + bb.x, acc[i][j][3] + bb.y);
            if (RELU) {
                v0.x = fmaxf(v0.x, 0.f); v0.y = fmaxf(v0.y, 0.f);
                v1.x = fmaxf(v1.x, 0.f); v1.y = fmaxf(v1.y, 0.f);
            }
            *(float2*)(Cb + (long)row * N + col)       = v0;
            *(float2*)(Cb + (long)(row + 8) * N + col) = v1;
        }
    }
}

// ---------------- softmax over rows (axis j of e1[b,i,j]) ----------------
__global__ void softmax_rows_kernel(const float* __restrict__ e,
                                    float* __restrict__ w)
{
    long row = blockIdx.x;               // b*L + i
    int t = threadIdx.x;                 // j (256 threads)
    float v = e[row * L + t];

    __shared__ float sm[8];
    float m = v;
#pragma unroll
    for (int s = 16; s; s >>= 1) m = fmaxf(m, __shfl_xor_sync(~0u, m, s));
    if ((t & 31) == 0) sm[t >> 5] = m;
    __syncthreads();
    m = sm[0];
#pragma unroll
    for (int k = 1; k < 8; k++) m = fmaxf(m, sm[k]);
    __syncthreads();

    float ex = __expf(v - m);
    float s = ex;
#pragma unroll
    for (int sh = 16; sh; sh >>= 1) s += __shfl_xor_sync(~0u, s, sh);
    if ((t & 31) == 0) sm[t >> 5] = s;
    __syncthreads();
    s = sm[0];
#pragma unroll
    for (int k = 1; k < 8; k++) s += sm[k];

    w[row * L + t] = ex * (1.f / s);
}

// ---------------- softmax over columns: w2[b,j,i] = softmax_i e[b,i,j] -----
__global__ void softmax_cols_kernel(const float* __restrict__ e,
                                    float* __restrict__ w2)
{
    int b  = blockIdx.x;
    int j0 = blockIdx.y * 32;
    int tx = threadIdx.x & 31;
    int ty = threadIdx.x >> 5;           // 0..7

    const float* eb = e + (long)b * L * L;
    float vals[32];
    float m = -1e30f;
#pragma unroll
    for (int r = 0; r < 32; r++) {
        float v = eb[(long)(ty + 8 * r) * L + j0 + tx];
        vals[r] = v;
        m = fmaxf(m, v);
    }
    __shared__ float red[8][33];
    red[ty][tx] = m;
    __syncthreads();
    if (ty == 0) {
        float mm = red[0][tx];
#pragma unroll
        for (int t = 1; t < 8; t++) mm = fmaxf(mm, red[t][tx]);
        red[0][tx] = mm;
    }
    __syncthreads();
    m = red[0][tx];
    __syncthreads();

    float s = 0.f;
#pragma unroll
    for (int r = 0; r < 32; r++) { vals[r] = __expf(vals[r] - m); s += vals[r]; }
    red[ty][tx] = s;
    __syncthreads();
    if (ty == 0) {
        float ss = red[0][tx];
#pragma unroll
        for (int t = 1; t < 8; t++) ss += red[t][tx];
        red[0][tx] = ss;
    }
    __syncthreads();
    float inv = 1.f / red[0][tx];

    float* wb = w2 + (long)b * L * L;
#pragma unroll
    for (int r = 0; r < 32; r++)
        wb[(long)(j0 + tx) * L + (ty + 8 * r)] = vals[r] * inv;
}

// ---------------- column sum over seq: s[b,h] = sum_i cmp[b,i,h] -----------
__global__ void colsum_kernel(const float* __restrict__ cmp,
                              float* __restrict__ s, int offset)
{
    int b = blockIdx.x;
    int h = blockIdx.y * 256 + threadIdx.x;
    const float* p = cmp + (long)b * L * HID + h;
    float acc = 0.f;
#pragma unroll 4
    for (int i = 0; i < L; i++) acc += p[(long)i * HID];
    s[(long)b * (2 * HID) + offset + h] = acc;
}

// ---------------- final linear: out[b,o] = agg2[b,:] . fin_w[o,:] + b ------
__global__ void final_kernel(const float* __restrict__ h,
                             const float* __restrict__ w,
                             const float* __restrict__ bias,
                             float* __restrict__ out)
{
    int b = blockIdx.x;
    int o = threadIdx.x >> 5;            // 3 warps
    int lane = threadIdx.x & 31;
    float acc = 0.f;
    for (int k = lane; k < HID; k += 32)
        acc += h[(long)b * HID + k] * w[(long)o * HID + k];
#pragma unroll
    for (int s = 16; s; s >>= 1) acc += __shfl_xor_sync(~0u, acc, s);
    if (lane == 0) out[b * 3 + o] = acc + bias[o];
}

// ---------------- host ----------------
static float* symaddr(const void* sym)
{
    void* p = nullptr;
    cudaGetSymbolAddress(&p, sym);
    return (float*)p;
}

extern "C" void kernel_launch(void* const* d_in, const int* in_sizes, int n_in,
                              void* d_out, int out_size)
{
    (void)in_sizes; (void)n_in; (void)out_size;

    const float* sent1 = (const float*)d_in[0];
    const float* sent2 = (const float*)d_in[1];
    const float* f_w1  = (const float*)d_in[2];
    const float* f_b1  = (const float*)d_in[3];
    const float* f_w2  = (const float*)d_in[4];
    const float* f_b2  = (const float*)d_in[5];
    const float* gw1   = (const float*)d_in[6];
    const float* gb1   = (const float*)d_in[7];
    const float* gw2   = (const float*)d_in[8];
    const float* gb2   = (const float*)d_in[9];
    const float* hw1   = (const float*)d_in[10];
    const float* hb1   = (const float*)d_in[11];
    const float* hw2   = (const float*)d_in[12];
    const float* hb2   = (const float*)d_in[13];
    const float* finw  = (const float*)d_in[14];
    const float* finb  = (const float*)d_in[15];
    float* out = (float*)d_out;

    float* f1   = symaddr(g_f1);
    float* f2   = symaddr(g_f2);
    float* bufH = symaddr(g_bufH);
    float* bufB = symaddr(g_bufB);
    float* e    = symaddr(g_e);
    float* w1a  = symaddr(g_w1);
    float* w2a  = symaddr(g_w2);
    float* att1 = symaddr(g_att1);
    float* att2 = symaddr(g_att2);
    float* sbuf = symaddr(g_s);
    float* agg1 = symaddr(g_agg1);
    float* agg2 = symaddr(g_agg2);

    // C = relu(A @ W^T + b),  A:[M,K], W:[N,K]
    auto mlp = [](const float* A, const float* W, const float* b, float* C,
                  int M, int N, int K) {
        dim3 grid(N / 128, M / 128, 1);
        mma_gemm<true, true, true, false><<<grid, 256>>>(
            A, nullptr, W, b, C, N, K, 0, 0, 0);
    };
    // C = relu(concat(att, sent) @ W^T + b) — fused concat (K = 1024)
    auto mlp_split = [](const float* att, const float* sent, const float* W,
                        const float* b, float* C, int M, int N) {
        dim3 grid(N / 128, M / 128, 1);
        mma_gemm<true, true, true, true><<<grid, 256>>>(
            att, sent, W, b, C, N, 2 * EMB, 0, 0, 0);
    };

    // ---- Attend: f MLP on both sentences ----
    mlp(sent1, f_w1, f_b1, bufH, TOK, HID, EMB);
    mlp(bufH,  f_w2, f_b2, f1,   TOK, HID, HID);
    mlp(sent2, f_w1, f_b1, bufH, TOK, HID, EMB);
    mlp(bufH,  f_w2, f_b2, f2,   TOK, HID, HID);

    // e1[b] = f1[b] @ f2[b]^T   (batched NT, 256x256x1024)
    {
        dim3 grid(L / 128, L / 128, NB);
        mma_gemm<true, false, false, false><<<grid, 256>>>(
            f1, nullptr, f2, nullptr, e, L, HID,
            (long)L * HID, (long)L * HID, (long)L * L);
    }

    softmax_rows_kernel<<<NB * L, 256>>>(e, w1a);
    softmax_cols_kernel<<<dim3(NB, L / 32), 256>>>(e, w2a);

    // att1[b] = w1a[b] @ sent2[b], att2[b] = w2a[b] @ sent1[b] (batched NN)
    {
        dim3 grid(EMB / 128, L / 128, NB);
        mma_gemm<false, false, false, false><<<grid, 256>>>(
            w1a, nullptr, sent2, nullptr, att1, EMB, L,
            (long)L * L, (long)L * EMB, (long)L * EMB);
        mma_gemm<false, false, false, false><<<grid, 256>>>(
            w2a, nullptr, sent1, nullptr, att2, EMB, L,
            (long)L * L, (long)L * EMB, (long)L * EMB);
    }

    // ---- Compare + aggregate-sum, sentence 1 ----
    mlp_split(att1, sent1, gw1, gb1, bufH, TOK, HID);
    mlp(bufH, gw2, gb2, bufB, TOK, HID, HID);
    colsum_kernel<<<dim3(NB, HID / 256), 256>>>(bufB, sbuf, 0);

    // ---- Compare + aggregate-sum, sentence 2 ----
    mlp_split(att2, sent2, gw1, gb1, bufH, TOK, HID);
    mlp(bufH, gw2, gb2, bufB, TOK, HID, HID);
    colsum_kernel<<<dim3(NB, HID / 256), 256>>>(bufB, sbuf, HID);

    // ---- Aggregate MLP + final linear ----
    mlp(sbuf, hw1, hb1, agg1, NB, HID, 2 * HID);
    mlp(agg1, hw2, hb2, agg2, NB, HID, HID);
    final_kernel<<<NB, 96>>>(agg2, finw, finb, out);
}

// round 14
// speedup vs baseline: 3.7212x; 1.7464x over previous
#include <cuda_runtime.h>
#include <cstdint>

// ---------------- problem constants ----------------
#define NB   128            // batch
#define L    256            // seq len (both sentences)
#define EMB  512
#define HID  1024
#define TOK  (NB * L)       // 32768 tokens per sentence

// ---------------- scratch (device globals; no allocations) ----------------
__device__ __align__(16) float g_f1  [TOK * HID];
__device__ __align__(16) float g_f2  [TOK * HID];
__device__ __align__(16) float g_bufH[TOK * HID];
__device__ __align__(16) float g_bufB[TOK * HID];
__device__ __align__(16) float g_e   [NB * L * L];
__device__ __align__(16) float g_w1  [NB * L * L];   // row softmax [B,L1,L2]
__device__ __align__(16) float g_w2  [NB * L * L];   // col softmax [B,L2,L1]
__device__ __align__(16) float g_att1[NB * L * EMB];
__device__ __align__(16) float g_att2[NB * L * EMB];
__device__ __align__(16) float g_sT1 [NB * EMB * L]; // sent1^T per batch
__device__ __align__(16) float g_sT2 [NB * EMB * L]; // sent2^T per batch
__device__ __align__(16) float g_s   [NB * 2 * HID]; // [s1 | s2]
__device__ __align__(16) float g_agg1[NB * HID];
__device__ __align__(16) float g_agg2[NB * HID];

// ---------------- PTX helpers ----------------
__device__ __forceinline__ uint32_t smem_u32(const void* p)
{
    uint32_t a;
    asm("{ .reg .u64 t; cvta.to.shared.u64 t, %1; cvt.u32.u64 %0, t; }"
        : "=r"(a) : "l"(p));
    return a;
}

__device__ __forceinline__ unsigned f2t(unsigned xbits)
{
    unsigned u;
    asm("cvt.rna.tf32.f32 %0, %1;" : "=r"(u) : "r"(xbits));
    return u;
}

__device__ __forceinline__ void cp_async16(uint32_t dst, const void* src)
{
    asm volatile("cp.async.cg.shared.global [%0], [%1], 16;"
                 :: "r"(dst), "l"(src) : "memory");
}
__device__ __forceinline__ void cp_commit()
{
    asm volatile("cp.async.commit_group;" ::: "memory");
}
template<int N>
__device__ __forceinline__ void cp_wait()
{
    asm volatile("cp.async.wait_group %0;" :: "n"(N) : "memory");
}

__device__ __forceinline__ void ldsm4(unsigned* r, uint32_t addr)
{
    asm volatile("ldmatrix.sync.aligned.m8n8.x4.shared.b16 {%0,%1,%2,%3}, [%4];"
                 : "=r"(r[0]), "=r"(r[1]), "=r"(r[2]), "=r"(r[3]) : "r"(addr));
}

__device__ __forceinline__ void mma_tf32(float* c, const unsigned* a, const unsigned* b)
{
    asm volatile(
        "mma.sync.aligned.m16n8k8.row.col.f32.tf32.tf32.f32 "
        "{%0,%1,%2,%3},{%4,%5,%6,%7},{%8,%9},{%0,%1,%2,%3};"
        : "+f"(c[0]), "+f"(c[1]), "+f"(c[2]), "+f"(c[3])
        : "r"(a[0]), "r"(a[1]), "r"(a[2]), "r"(a[3]), "r"(b[0]), "r"(b[1]));
}

// ---------------- tf32 mma.sync GEMM, ldmatrix + cp.async ----------------
// C = act(A @ B^T + bias); A:[M,K] row-major, B:[N,K] row-major (NT form).
// SPLIT: A = concat(A[:,0:512], A2[:,0:512]) along K (fused compare concat).
// CTA tile 128x256, 8 warps (2x4) of 64x64; BK=32; 3-stage cp.async pipeline.
// SMEM tiles row-major fp32 with XOR-128B swizzle (conflict-free STS via
// cp.async AND conflict-free LDSM); fragments via ldmatrix.x4.b16 (tf32 rows
// viewed as b16: lane's b16-pair == the fp32 word at (l/4, l%4) == the mma
// fragment element). cvt.rna.tf32 applied on fragment registers.
#define BM 128
#define BN 256
#define BK 32
#define STAGE_BYTES ((BM + BN) * BK * 4)   // 49152
#define NSTAGE 3
#define SMEM_DYN (NSTAGE * STAGE_BYTES + 1024)

template<bool BIAS, bool RELU, bool SPLIT>
__global__ void __launch_bounds__(256, 1)
mma2_gemm(const float* __restrict__ A, const float* __restrict__ A2,
          const float* __restrict__ B, const float* __restrict__ bias,
          float* __restrict__ C, int N, int K,
          long sA, long sB, long sC)
{
    extern __shared__ char dsm[];
    char* abase = (char*)(((uintptr_t)dsm + 1023) & ~(uintptr_t)1023);
    const uint32_t smem0 = smem_u32(abase);

    const int tid  = threadIdx.x;
    const int lane = tid & 31;
    const int warp = tid >> 5;
    const int wm   = warp >> 2;          // 0..1  (64-row slice)
    const int wn   = warp & 3;           // 0..3  (64-col slice)
    const int bx = blockIdx.x, by = blockIdx.y, bz = blockIdx.z;

    // global operand bases
    const float* Ab;
    const float* A2b = nullptr;
    if (SPLIT) {
        Ab  = A  + (long)by * BM * EMB;
        A2b = A2 + (long)by * BM * EMB;
    } else {
        Ab = A + bz * sA + (long)by * BM * (long)K;
    }
    const float* Bb = B + bz * sB + (long)bx * BN * (long)K;
    float* Cb = C + bz * sC + (long)by * BM * (long)N + bx * BN;

    // ---- per-lane ldmatrix geometry (byte offsets within a tile) ----
    // A frag (m16k8) tiles g: row += (g&1)*8, colbyte += (g>>1)*16
    // B frag pair (two n8k8) tiles g: row += (g>>1)*8, colbyte += (g&1)*16
    const int g  = lane >> 3;
    const int lr = lane & 7;
    const uint32_t swz = (uint32_t)lr << 4;
    const uint32_t aRow = (uint32_t)(wm * 64 + ((g & 1) << 3) + lr) * 128
                        + ((uint32_t)(g >> 1) << 4);
    const uint32_t bRow = (uint32_t)(wn * 64 + ((g >> 1) << 3) + lr) * 128
                        + ((uint32_t)(g & 1) << 4);

    // ---- staging: cp.async 16B copies, swizzled row-major ----
    auto issue_stage = [&](int k0, int s) {
        uint32_t dstA = smem0 + s * STAGE_BYTES;
        uint32_t dstB = dstA + BM * BK * 4;
        const float* Asrc;
        long strideA;
        if (SPLIT) {
            Asrc = (k0 < EMB) ? (Ab + k0) : (A2b + (k0 - EMB));
            strideA = EMB;
        } else {
            Asrc = Ab + k0;
            strideA = K;
        }
#pragma unroll
        for (int it = 0; it < 4; it++) {              // A: 128x32 = 1024 f4
            int id = it * 256 + tid;
            int row = id >> 3, c4 = (id & 7) << 2;
            uint32_t d = dstA + (((uint32_t)row * 128 + ((uint32_t)c4 << 2))
                                 ^ (((uint32_t)row & 7) << 4));
            cp_async16(d, Asrc + (long)row * strideA + c4);
        }
#pragma unroll
        for (int it = 0; it < 8; it++) {              // B: 256x32 = 2048 f4
            int id = it * 256 + tid;
            int row = id >> 3, c4 = (id & 7) << 2;
            uint32_t d = dstB + (((uint32_t)row * 128 + ((uint32_t)c4 << 2))
                                 ^ (((uint32_t)row & 7) << 4));
            cp_async16(d, Bb + (long)row * K + k0 + c4);
        }
        cp_commit();
    };

    // ---- accumulators ----
    float acc[4][8][4];
#pragma unroll
    for (int i = 0; i < 4; i++)
#pragma unroll
        for (int j = 0; j < 8; j++)
#pragma unroll
            for (int q = 0; q < 4; q++) acc[i][j][q] = 0.f;

    // ---- compute one 32-wide k-stage ----
    auto compute = [&](int s) {
        uint32_t baseA = smem0 + s * STAGE_BYTES;
        uint32_t baseB = baseA + BM * BK * 4;
#pragma unroll
        for (int kt = 0; kt < 4; kt++) {
            unsigned a[4][4], b[4][4];
#pragma unroll
            for (int mt = 0; mt < 4; mt++)
                ldsm4(a[mt], baseA + ((aRow + mt * 2048 + kt * 32) ^ swz));
#pragma unroll
            for (int np = 0; np < 4; np++)
                ldsm4(b[np], baseB + ((bRow + np * 2048 + kt * 32) ^ swz));
#pragma unroll
            for (int mt = 0; mt < 4; mt++)
#pragma unroll
                for (int q = 0; q < 4; q++) a[mt][q] = f2t(a[mt][q]);
#pragma unroll
            for (int np = 0; np < 4; np++)
#pragma unroll
                for (int q = 0; q < 4; q++) b[np][q] = f2t(b[np][q]);
#pragma unroll
            for (int mt = 0; mt < 4; mt++)
#pragma unroll
                for (int np = 0; np < 4; np++) {
                    mma_tf32(acc[mt][2 * np + 0], a[mt], &b[np][0]);
                    mma_tf32(acc[mt][2 * np + 1], a[mt], &b[np][2]);
                }
        }
    };

    // ---- pipelined mainloop ----
    const int nK = K / BK;
    issue_stage(0, 0);
    if (nK > 1) issue_stage(BK, 1);
    cp_wait<1>();
    __syncthreads();

    for (int i = 0; i < nK; i++) {
        compute(i % NSTAGE);
        __syncthreads();
        if (i + 2 < nK) {
            issue_stage((i + 2) * BK, (i + 2) % NSTAGE);
            cp_wait<1>();
        } else {
            cp_wait<0>();
        }
        __syncthreads();
    }

    // ---- epilogue: bias + relu + float2 stores (direct) ----
    const int g4 = lane >> 2, t = lane & 3;
#pragma unroll
    for (int j = 0; j < 8; j++) {
        int col = wn * 64 + j * 8 + t * 2;
        float2 bb = make_float2(0.f, 0.f);
        if (BIAS) bb = *(const float2*)(bias + (long)bx * BN + col);
#pragma unroll
        for (int i = 0; i < 4; i++) {
            int row = wm * 64 + i * 16 + g4;
            float2 v0 = make_float2(acc[i][j][0] + bb.x, acc[i][j][1] + bb.y);
            float2 v1 = make_float2(acc[i][j][2] + bb.x, acc[i][j][3] + bb.y);
            if (RELU) {
                v0.x = fmaxf(v0.x, 0.f); v0.y = fmaxf(v0.y, 0.f);
                v1.x = fmaxf(v1.x, 0.f); v1.y = fmaxf(v1.y, 0.f);
            }
            *(float2*)(Cb + (long)row * N + col)       = v0;
            *(float2*)(Cb + (long)(row + 8) * N + col) = v1;
        }
    }
}

// ---------------- per-batch transpose: [L,EMB] -> [EMB,L] ----------------
__global__ void transpose_kernel(const float* __restrict__ in,
                                 float* __restrict__ out)
{
    __shared__ float t[32][33];
    int b  = blockIdx.z;
    int r0 = blockIdx.y * 32;            // L dim
    int c0 = blockIdx.x * 32;            // EMB dim
    const float* ib = in + (long)b * L * EMB;
    float* ob = out + (long)b * EMB * L;
    int x = threadIdx.x, y = threadIdx.y;
#pragma unroll
    for (int i = 0; i < 32; i += 8)
        t[y + i][x] = ib[(long)(r0 + y + i) * EMB + c0 + x];
    __syncthreads();
#pragma unroll
    for (int i = 0; i < 32; i += 8)
        ob[(long)(c0 + y + i) * L + r0 + x] = t[x][y + i];
}

// ---------------- softmax over rows (axis j of e1[b,i,j]) ----------------
__global__ void softmax_rows_kernel(const float* __restrict__ e,
                                    float* __restrict__ w)
{
    long row = blockIdx.x;               // b*L + i
    int t = threadIdx.x;                 // j (256 threads)
    float v = e[row * L + t];

    __shared__ float sm[8];
    float m = v;
#pragma unroll
    for (int s = 16; s; s >>= 1) m = fmaxf(m, __shfl_xor_sync(~0u, m, s));
    if ((t & 31) == 0) sm[t >> 5] = m;
    __syncthreads();
    m = sm[0];
#pragma unroll
    for (int k = 1; k < 8; k++) m = fmaxf(m, sm[k]);
    __syncthreads();

    float ex = __expf(v - m);
    float s = ex;
#pragma unroll
    for (int sh = 16; sh; sh >>= 1) s += __shfl_xor_sync(~0u, s, sh);
    if ((t & 31) == 0) sm[t >> 5] = s;
    __syncthreads();
    s = sm[0];
#pragma unroll
    for (int k = 1; k < 8; k++) s += sm[k];

    w[row * L + t] = ex * (1.f / s);
}

// ---------------- softmax over columns: w2[b,j,i] = softmax_i e[b,i,j] -----
__global__ void softmax_cols_kernel(const float* __restrict__ e,
                                    float* __restrict__ w2)
{
    int b  = blockIdx.x;
    int j0 = blockIdx.y * 32;
    int tx = threadIdx.x & 31;
    int ty = threadIdx.x >> 5;           // 0..7

    const float* eb = e + (long)b * L * L;
    float vals[32];
    float m = -1e30f;
#pragma unroll
    for (int r = 0; r < 32; r++) {
        float v = eb[(long)(ty + 8 * r) * L + j0 + tx];
        vals[r] = v;
        m = fmaxf(m, v);
    }
    __shared__ float red[8][33];
    red[ty][tx] = m;
    __syncthreads();
    if (ty == 0) {
        float mm = red[0][tx];
#pragma unroll
        for (int t = 1; t < 8; t++) mm = fmaxf(mm, red[t][tx]);
        red[0][tx] = mm;
    }
    __syncthreads();
    m = red[0][tx];
    __syncthreads();

    float s = 0.f;
#pragma unroll
    for (int r = 0; r < 32; r++) { vals[r] = __expf(vals[r] - m); s += vals[r]; }
    red[ty][tx] = s;
    __syncthreads();
    if (ty == 0) {
        float ss = red[0][tx];
#pragma unroll
        for (int t = 1; t < 8; t++) ss += red[t][tx];
        red[0][tx] = ss;
    }
    __syncthreads();
    float inv = 1.f / red[0][tx];

    float* wb = w2 + (long)b * L * L;
#pragma unroll
    for (int r = 0; r < 32; r++)
        wb[(long)(j0 + tx) * L + (ty + 8 * r)] = vals[r] * inv;
}

// ---------------- column sum over seq: s[b,h] = sum_i cmp[b,i,h] -----------
__global__ void colsum_kernel(const float* __restrict__ cmp,
                              float* __restrict__ s, int offset)
{
    int b = blockIdx.x;
    int h = blockIdx.y * 256 + threadIdx.x;
    const float* p = cmp + (long)b * L * HID + h;
    float acc = 0.f;
#pragma unroll 4
    for (int i = 0; i < L; i++) acc += p[(long)i * HID];
    s[(long)b * (2 * HID) + offset + h] = acc;
}

// ---------------- final linear: out[b,o] = agg2[b,:] . fin_w[o,:] + b ------
__global__ void final_kernel(const float* __restrict__ h,
                             const float* __restrict__ w,
                             const float* __restrict__ bias,
                             float* __restrict__ out)
{
    int b = blockIdx.x;
    int o = threadIdx.x >> 5;            // 3 warps
    int lane = threadIdx.x & 31;
    float acc = 0.f;
    for (int k = lane; k < HID; k += 32)
        acc += h[(long)b * HID + k] * w[(long)o * HID + k];
#pragma unroll
    for (int s = 16; s; s >>= 1) acc += __shfl_xor_sync(~0u, acc, s);
    if (lane == 0) out[b * 3 + o] = acc + bias[o];
}

// ---------------- host ----------------
static float* symaddr(const void* sym)
{
    void* p = nullptr;
    cudaGetSymbolAddress(&p, sym);
    return (float*)p;
}

extern "C" void kernel_launch(void* const* d_in, const int* in_sizes, int n_in,
                              void* d_out, int out_size)
{
    (void)in_sizes; (void)n_in; (void)out_size;

    const float* sent1 = (const float*)d_in[0];
    const float* sent2 = (const float*)d_in[1];
    const float* f_w1  = (const float*)d_in[2];
    const float* f_b1  = (const float*)d_in[3];
    const float* f_w2  = (const float*)d_in[4];
    const float* f_b2  = (const float*)d_in[5];
    const float* gw1   = (const float*)d_in[6];
    const float* gb1   = (const float*)d_in[7];
    const float* gw2   = (const float*)d_in[8];
    const float* gb2   = (const float*)d_in[9];
    const float* hw1   = (const float*)d_in[10];
    const float* hb1   = (const float*)d_in[11];
    const float* hw2   = (const float*)d_in[12];
    const float* hb2   = (const float*)d_in[13];
    const float* finw  = (const float*)d_in[14];
    const float* finb  = (const float*)d_in[15];
    float* out = (float*)d_out;

    float* f1   = symaddr(g_f1);
    float* f2   = symaddr(g_f2);
    float* bufH = symaddr(g_bufH);
    float* bufB = symaddr(g_bufB);
    float* e    = symaddr(g_e);
    float* w1a  = symaddr(g_w1);
    float* w2a  = symaddr(g_w2);
    float* att1 = symaddr(g_att1);
    float* att2 = symaddr(g_att2);
    float* sT1  = symaddr(g_sT1);
    float* sT2  = symaddr(g_sT2);
    float* sbuf = symaddr(g_s);
    float* agg1 = symaddr(g_agg1);
    float* agg2 = symaddr(g_agg2);

    cudaFuncSetAttribute((const void*)mma2_gemm<true, true, false>,
                         cudaFuncAttributeMaxDynamicSharedMemorySize, SMEM_DYN);
    cudaFuncSetAttribute((const void*)mma2_gemm<true, true, true>,
                         cudaFuncAttributeMaxDynamicSharedMemorySize, SMEM_DYN);
    cudaFuncSetAttribute((const void*)mma2_gemm<false, false, false>,
                         cudaFuncAttributeMaxDynamicSharedMemorySize, SMEM_DYN);

    // C = relu(A @ W^T + b),  A:[M,K], W:[N,K]
    auto mlp = [](const float* A, const float* W, const float* b, float* C,
                  int M, int N, int K) {
        dim3 grid(N / BN, M / BM, 1);
        mma2_gemm<true, true, false><<<grid, 256, SMEM_DYN>>>(
            A, nullptr, W, b, C, N, K, 0, 0, 0);
    };
    // C = relu(concat(att, sent) @ W^T + b), K = 1024, fused concat
    auto mlp_split = [](const float* att, const float* sent, const float* W,
                        const float* b, float* C, int M, int N) {
        dim3 grid(N / BN, M / BM, 1);
        mma2_gemm<true, true, true><<<grid, 256, SMEM_DYN>>>(
            att, sent, W, b, C, N, 2 * EMB, 0, 0, 0);
    };

    // ---- transposes for the attention @ sentence products ----
    {
        dim3 tg(EMB / 32, L / 32, NB);
        transpose_kernel<<<tg, dim3(32, 8)>>>(sent1, sT1);
        transpose_kernel<<<tg, dim3(32, 8)>>>(sent2, sT2);
    }

    // ---- Attend: f MLP on both sentences ----
    mlp(sent1, f_w1, f_b1, bufH, TOK, HID, EMB);
    mlp(bufH,  f_w2, f_b2, f1,   TOK, HID, HID);
    mlp(sent2, f_w1, f_b1, bufH, TOK, HID, EMB);
    mlp(bufH,  f_w2, f_b2, f2,   TOK, HID, HID);

    // e1[b] = f1[b] @ f2[b]^T   (batched NT, 256x256x1024)
    {
        dim3 grid(L / BN, L / BM, NB);
        mma2_gemm<false, false, false><<<grid, 256, SMEM_DYN>>>(
            f1, nullptr, f2, nullptr, e, L, HID,
            (long)L * HID, (long)L * HID, (long)L * L);
    }

    softmax_rows_kernel<<<NB * L, 256>>>(e, w1a);
    softmax_cols_kernel<<<dim3(NB, L / 32), 256>>>(e, w2a);

    // att1[b] = w1a[b] @ sT2[b]^T,  att2[b] = w2a[b] @ sT1[b]^T
    // (sT is [EMB, L] K-major => NT form, M=256, N=512, K=256)
    {
        dim3 grid(EMB / BN, L / BM, NB);
        mma2_gemm<false, false, false><<<grid, 256, SMEM_DYN>>>(
            w1a, nullptr, sT2, nullptr, att1, EMB, L,
            (long)L * L, (long)EMB * L, (long)L * EMB);
        mma2_gemm<false, false, false><<<grid, 256, SMEM_DYN>>>(
            w2a, nullptr, sT1, nullptr, att2, EMB, L,
            (long)L * L, (long)EMB * L, (long)L * EMB);
    }

    // ---- Compare + aggregate-sum, sentence 1 ----
    mlp_split(att1, sent1, gw1, gb1, bufH, TOK, HID);
    mlp(bufH, gw2, gb2, bufB, TOK, HID, HID);
    colsum_kernel<<<dim3(NB, HID / 256), 256>>>(bufB, sbuf, 0);

    // ---- Compare + aggregate-sum, sentence 2 ----
    mlp_split(att2, sent2, gw1, gb1, bufH, TOK, HID);
    mlp(bufH, gw2, gb2, bufB, TOK, HID, HID);
    colsum_kernel<<<dim3(NB, HID / 256), 256>>>(bufB, sbuf, HID);

    // ---- Aggregate MLP + final linear ----
    mlp(sbuf, hw1, hb1, agg1, NB, HID, 2 * HID);
    mlp(agg1, hw2, hb2, agg2, NB, HID, HID);
    final_kernel<<<NB, 96>>>(agg2, finw, finb, out);
}

// round 16
// speedup vs baseline: 4.0895x; 1.0990x over previous
#include <cuda_runtime.h>
#include <cstdint>

// ---------------- problem constants ----------------
#define NB   128            // batch
#define L    256            // seq len (both sentences)
#define EMB  512
#define HID  1024
#define TOK  (NB * L)       // 32768 tokens per sentence

// ---------------- scratch (device globals; no allocations) ----------------
__device__ __align__(16) float g_f1  [TOK * HID];
__device__ __align__(16) float g_f2  [TOK * HID];
__device__ __align__(16) float g_bufH[TOK * HID];
__device__ __align__(16) float g_bufB[TOK * HID];
__device__ __align__(16) float g_e   [NB * L * L];
__device__ __align__(16) float g_w1  [NB * L * L];   // row softmax [B,L1,L2]
__device__ __align__(16) float g_w2  [NB * L * L];   // col softmax [B,L2,L1]
__device__ __align__(16) float g_att1[NB * L * EMB];
__device__ __align__(16) float g_att2[NB * L * EMB];
__device__ __align__(16) float g_sT1 [NB * EMB * L]; // sent1^T (rounded)
__device__ __align__(16) float g_sT2 [NB * EMB * L]; // sent2^T (rounded)
__device__ __align__(16) float g_s   [NB * 2 * HID]; // [s1 | s2] (rounded)
__device__ __align__(16) float g_agg1[NB * HID];
__device__ __align__(16) float g_agg2[NB * HID];
// tf32-prerounded copies of raw GEMM operands
__device__ __align__(16) float g_s1r [TOK * EMB];
__device__ __align__(16) float g_s2r [TOK * EMB];
__device__ __align__(16) float g_fw1r[HID * EMB];
__device__ __align__(16) float g_fw2r[HID * HID];
__device__ __align__(16) float g_gw1r[HID * 2 * EMB];
__device__ __align__(16) float g_gw2r[HID * HID];
__device__ __align__(16) float g_hw1r[HID * 2 * HID];
__device__ __align__(16) float g_hw2r[HID * HID];

// ---------------- PTX helpers ----------------
__device__ __forceinline__ uint32_t smem_u32(const void* p)
{
    uint32_t a;
    asm("{ .reg .u64 t; cvta.to.shared.u64 t, %1; cvt.u32.u64 %0, t; }"
        : "=r"(a) : "l"(p));
    return a;
}

__device__ __forceinline__ float f2t_f(float x)
{
    unsigned u;
    asm("cvt.rna.tf32.f32 %0, %1;" : "=r"(u) : "f"(x));
    return __uint_as_float(u);
}

__device__ __forceinline__ void cp_async16(uint32_t dst, const void* src)
{
    asm volatile("cp.async.cg.shared.global [%0], [%1], 16;"
                 :: "r"(dst), "l"(src) : "memory");
}
__device__ __forceinline__ void cp_commit()
{
    asm volatile("cp.async.commit_group;" ::: "memory");
}
template<int N>
__device__ __forceinline__ void cp_wait()
{
    asm volatile("cp.async.wait_group %0;" :: "n"(N) : "memory");
}

__device__ __forceinline__ void ldsm4(unsigned* r, uint32_t addr)
{
    asm volatile("ldmatrix.sync.aligned.m8n8.x4.shared.b16 {%0,%1,%2,%3}, [%4];"
                 : "=r"(r[0]), "=r"(r[1]), "=r"(r[2]), "=r"(r[3]) : "r"(addr));
}

__device__ __forceinline__ void mma_tf32(float* c, const unsigned* a, const unsigned* b)
{
    asm volatile(
        "mma.sync.aligned.m16n8k8.row.col.f32.tf32.tf32.f32 "
        "{%0,%1,%2,%3},{%4,%5,%6,%7},{%8,%9},{%0,%1,%2,%3};"
        : "+f"(c[0]), "+f"(c[1]), "+f"(c[2]), "+f"(c[3])
        : "r"(a[0]), "r"(a[1]), "r"(a[2]), "r"(a[3]), "r"(b[0]), "r"(b[1]));
}

// ---------------- tf32 round-copy (one-time operand preprocessing) --------
__global__ void round_copy_kernel(const float* __restrict__ in,
                                  float* __restrict__ out, int n4)
{
    int i = blockIdx.x * 256 + threadIdx.x;
    if (i < n4) {
        float4 v = *(const float4*)(in + 4 * (long)i);
        v.x = f2t_f(v.x); v.y = f2t_f(v.y);
        v.z = f2t_f(v.z); v.w = f2t_f(v.w);
        *(float4*)(out + 4 * (long)i) = v;
    }
}

// ---------------- tf32 mma.sync GEMM, ldmatrix + cp.async ----------------
// C = act(A @ B^T + bias); A:[M,K] row-major, B:[N,K] row-major (NT form).
// ALL operands must already be tf32-rounded in memory (mainloop has no cvt).
// SPLIT: A = concat(A[:,0:512], A2[:,0:512]) along K (fused compare concat).
// CVT: round outputs to tf32 in the epilogue (for GEMM-feeding outputs).
// CTA tile 128x256, 8 warps (2x4) of 64x64; BK=32; 3-stage cp.async pipeline
// with the EXACT loop structure of the proven R14 kernel. XOR-128B swizzled
// row-major tiles; fragments via ldmatrix.x4.b16.
#define BM 128
#define BN 256
#define BK 32
#define STAGE_BYTES ((BM + BN) * BK * 4)   // 49152
#define NSTAGE 3
#define SMEM_DYN (NSTAGE * STAGE_BYTES + 1024)

template<bool BIAS, bool RELU, bool SPLIT, bool CVT>
__global__ void __launch_bounds__(256, 1)
mma2_gemm(const float* __restrict__ A, const float* __restrict__ A2,
          const float* __restrict__ B, const float* __restrict__ bias,
          float* __restrict__ C, int N, int K,
          long sA, long sB, long sC)
{
    extern __shared__ char dsm[];
    char* abase = (char*)(((uintptr_t)dsm + 1023) & ~(uintptr_t)1023);
    const uint32_t smem0 = smem_u32(abase);

    const int tid  = threadIdx.x;
    const int lane = tid & 31;
    const int warp = tid >> 5;
    const int wm   = warp >> 2;          // 0..1  (64-row slice)
    const int wn   = warp & 3;           // 0..3  (64-col slice)
    const int bx = blockIdx.x, by = blockIdx.y, bz = blockIdx.z;

    // global operand bases
    const float* Ab;
    const float* A2b = nullptr;
    if (SPLIT) {
        Ab  = A  + (long)by * BM * EMB;
        A2b = A2 + (long)by * BM * EMB;
    } else {
        Ab = A + bz * sA + (long)by * BM * (long)K;
    }
    const float* Bb = B + bz * sB + (long)bx * BN * (long)K;
    float* Cb = C + bz * sC + (long)by * BM * (long)N + bx * BN;

    // ---- per-lane ldmatrix geometry (byte offsets within a tile) ----
    const int g  = lane >> 3;
    const int lr = lane & 7;
    const uint32_t swz = (uint32_t)lr << 4;
    const uint32_t aRow = (uint32_t)(wm * 64 + ((g & 1) << 3) + lr) * 128
                        + ((uint32_t)(g >> 1) << 4);
    const uint32_t bRow = (uint32_t)(wn * 64 + ((g >> 1) << 3) + lr) * 128
                        + ((uint32_t)(g & 1) << 4);

    // ---- staging: cp.async 16B copies, swizzled row-major ----
    auto issue_stage = [&](int k0, int s) {
        uint32_t dstA = smem0 + s * STAGE_BYTES;
        uint32_t dstB = dstA + BM * BK * 4;
        const float* Asrc;
        long strideA;
        if (SPLIT) {
            Asrc = (k0 < EMB) ? (Ab + k0) : (A2b + (k0 - EMB));
            strideA = EMB;
        } else {
            Asrc = Ab + k0;
            strideA = K;
        }
#pragma unroll
        for (int it = 0; it < 4; it++) {              // A: 128x32 = 1024 f4
            int id = it * 256 + tid;
            int row = id >> 3, c4 = (id & 7) << 2;
            uint32_t d = dstA + (((uint32_t)row * 128 + ((uint32_t)c4 << 2))
                                 ^ (((uint32_t)row & 7) << 4));
            cp_async16(d, Asrc + (long)row * strideA + c4);
        }
#pragma unroll
        for (int it = 0; it < 8; it++) {              // B: 256x32 = 2048 f4
            int id = it * 256 + tid;
            int row = id >> 3, c4 = (id & 7) << 2;
            uint32_t d = dstB + (((uint32_t)row * 128 + ((uint32_t)c4 << 2))
                                 ^ (((uint32_t)row & 7) << 4));
            cp_async16(d, Bb + (long)row * K + k0 + c4);
        }
        cp_commit();
    };

    // ---- accumulators ----
    float acc[4][8][4];
#pragma unroll
    for (int i = 0; i < 4; i++)
#pragma unroll
        for (int j = 0; j < 8; j++)
#pragma unroll
            for (int q = 0; q < 4; q++) acc[i][j][q] = 0.f;

    // ---- compute one 32-wide k-stage (NO cvt: operands pre-rounded) ----
    auto compute = [&](int s) {
        uint32_t baseA = smem0 + s * STAGE_BYTES;
        uint32_t baseB = baseA + BM * BK * 4;
#pragma unroll
        for (int kt = 0; kt < 4; kt++) {
            unsigned a[4][4], b[4][4];
#pragma unroll
            for (int mt = 0; mt < 4; mt++)
                ldsm4(a[mt], baseA + ((aRow + mt * 2048 + kt * 32) ^ swz));
#pragma unroll
            for (int np = 0; np < 4; np++)
                ldsm4(b[np], baseB + ((bRow + np * 2048 + kt * 32) ^ swz));
#pragma unroll
            for (int mt = 0; mt < 4; mt++)
#pragma unroll
                for (int np = 0; np < 4; np++) {
                    mma_tf32(acc[mt][2 * np + 0], a[mt], &b[np][0]);
                    mma_tf32(acc[mt][2 * np + 1], a[mt], &b[np][2]);
                }
        }
    };

    // ---- pipelined mainloop (EXACT R14 structure) ----
    const int nK = K / BK;
    issue_stage(0, 0);
    if (nK > 1) issue_stage(BK, 1);
    cp_wait<1>();
    __syncthreads();

    for (int i = 0; i < nK; i++) {
        compute(i % NSTAGE);
        __syncthreads();
        if (i + 2 < nK) {
            issue_stage((i + 2) * BK, (i + 2) % NSTAGE);
            cp_wait<1>();
        } else {
            cp_wait<0>();
        }
        __syncthreads();
    }

    // ---- epilogue: bias + relu (+ tf32 round) + float2 stores ----
    const int g4 = lane >> 2, t = lane & 3;
#pragma unroll
    for (int j = 0; j < 8; j++) {
        int col = wn * 64 + j * 8 + t * 2;
        float2 bb = make_float2(0.f, 0.f);
        if (BIAS) bb = *(const float2*)(bias + (long)bx * BN + col);
#pragma unroll
        for (int i = 0; i < 4; i++) {
            int row = wm * 64 + i * 16 + g4;
            float2 v0 = make_float2(acc[i][j][0] + bb.x, acc[i][j][1] + bb.y);
            float2 v1 = make_float2(acc[i][j][2] + bb.x, acc[i][j][3] + bb.y);
            if (RELU) {
                v0.x = fmaxf(v0.x, 0.f); v0.y = fmaxf(v0.y, 0.f);
                v1.x = fmaxf(v1.x, 0.f); v1.y = fmaxf(v1.y, 0.f);
            }
            if (CVT) {
                v0.x = f2t_f(v0.x); v0.y = f2t_f(v0.y);
                v1.x = f2t_f(v1.x); v1.y = f2t_f(v1.y);
            }
            *(float2*)(Cb + (long)row * N + col)       = v0;
            *(float2*)(Cb + (long)(row + 8) * N + col) = v1;
        }
    }
}

// ---------------- per-batch transpose: [L,EMB] -> [EMB,L], tf32-rounded ---
__global__ void transpose_kernel(const float* __restrict__ in,
                                 float* __restrict__ out)
{
    __shared__ float t[32][33];
    int b  = blockIdx.z;
    int r0 = blockIdx.y * 32;            // L dim
    int c0 = blockIdx.x * 32;            // EMB dim
    const float* ib = in + (long)b * L * EMB;
    float* ob = out + (long)b * EMB * L;
    int x = threadIdx.x, y = threadIdx.y;
#pragma unroll
    for (int i = 0; i < 32; i += 8)
        t[y + i][x] = ib[(long)(r0 + y + i) * EMB + c0 + x];
    __syncthreads();
#pragma unroll
    for (int i = 0; i < 32; i += 8)
        ob[(long)(c0 + y + i) * L + r0 + x] = f2t_f(t[x][y + i]);
}

// ---------------- softmax over rows, tf32-rounded output ----------------
__global__ void softmax_rows_kernel(const float* __restrict__ e,
                                    float* __restrict__ w)
{
    long row = blockIdx.x;               // b*L + i
    int t = threadIdx.x;                 // j (256 threads)
    float v = e[row * L + t];

    __shared__ float sm[8];
    float m = v;
#pragma unroll
    for (int s = 16; s; s >>= 1) m = fmaxf(m, __shfl_xor_sync(~0u, m, s));
    if ((t & 31) == 0) sm[t >> 5] = m;
    __syncthreads();
    m = sm[0];
#pragma unroll
    for (int k = 1; k < 8; k++) m = fmaxf(m, sm[k]);
    __syncthreads();

    float ex = __expf(v - m);
    float s = ex;
#pragma unroll
    for (int sh = 16; sh; sh >>= 1) s += __shfl_xor_sync(~0u, s, sh);
    if ((t & 31) == 0) sm[t >> 5] = s;
    __syncthreads();
    s = sm[0];
#pragma unroll
    for (int k = 1; k < 8; k++) s += sm[k];

    w[row * L + t] = f2t_f(ex * (1.f / s));
}

// ---------------- softmax over columns, tf32-rounded output ----------------
__global__ void softmax_cols_kernel(const float* __restrict__ e,
                                    float* __restrict__ w2)
{
    int b  = blockIdx.x;
    int j0 = blockIdx.y * 32;
    int tx = threadIdx.x & 31;
    int ty = threadIdx.x >> 5;           // 0..7

    const float* eb = e + (long)b * L * L;
    float vals[32];
    float m = -1e30f;
#pragma unroll
    for (int r = 0; r < 32; r++) {
        float v = eb[(long)(ty + 8 * r) * L + j0 + tx];
        vals[r] = v;
        m = fmaxf(m, v);
    }
    __shared__ float red[8][33];
    red[ty][tx] = m;
    __syncthreads();
    if (ty == 0) {
        float mm = red[0][tx];
#pragma unroll
        for (int t = 1; t < 8; t++) mm = fmaxf(mm, red[t][tx]);
        red[0][tx] = mm;
    }
    __syncthreads();
    m = red[0][tx];
    __syncthreads();

    float s = 0.f;
#pragma unroll
    for (int r = 0; r < 32; r++) { vals[r] = __expf(vals[r] - m); s += vals[r]; }
    red[ty][tx] = s;
    __syncthreads();
    if (ty == 0) {
        float ss = red[0][tx];
#pragma unroll
        for (int t = 1; t < 8; t++) ss += red[t][tx];
        red[0][tx] = ss;
    }
    __syncthreads();
    float inv = 1.f / red[0][tx];

    float* wb = w2 + (long)b * L * L;
#pragma unroll
    for (int r = 0; r < 32; r++)
        wb[(long)(j0 + tx) * L + (ty + 8 * r)] = f2t_f(vals[r] * inv);
}

// ---------------- column sum over seq, tf32-rounded output ----------------
__global__ void colsum_kernel(const float* __restrict__ cmp,
                              float* __restrict__ s, int offset)
{
    int b = blockIdx.x;
    int h = blockIdx.y * 256 + threadIdx.x;
    const float* p = cmp + (long)b * L * HID + h;
    float acc = 0.f;
#pragma unroll 4
    for (int i = 0; i < L; i++) acc += p[(long)i * HID];
    s[(long)b * (2 * HID) + offset + h] = f2t_f(acc);
}

// ---------------- final linear: out[b,o] = agg2[b,:] . fin_w[o,:] + b ------
__global__ void final_kernel(const float* __restrict__ h,
                             const float* __restrict__ w,
                             const float* __restrict__ bias,
                             float* __restrict__ out)
{
    int b = blockIdx.x;
    int o = threadIdx.x >> 5;            // 3 warps
    int lane = threadIdx.x & 31;
    float acc = 0.f;
    for (int k = lane; k < HID; k += 32)
        acc += h[(long)b * HID + k] * w[(long)o * HID + k];
#pragma unroll
    for (int s = 16; s; s >>= 1) acc += __shfl_xor_sync(~0u, acc, s);
    if (lane == 0) out[b * 3 + o] = acc + bias[o];
}

// ---------------- host ----------------
static float* symaddr(const void* sym)
{
    void* p = nullptr;
    cudaGetSymbolAddress(&p, sym);
    return (float*)p;
}

extern "C" void kernel_launch(void* const* d_in, const int* in_sizes, int n_in,
                              void* d_out, int out_size)
{
    (void)in_sizes; (void)n_in; (void)out_size;

    const float* sent1 = (const float*)d_in[0];
    const float* sent2 = (const float*)d_in[1];
    const float* f_w1  = (const float*)d_in[2];
    const float* f_b1  = (const float*)d_in[3];
    const float* f_w2  = (const float*)d_in[4];
    const float* f_b2  = (const float*)d_in[5];
    const float* gw1   = (const float*)d_in[6];
    const float* gb1   = (const float*)d_in[7];
    const float* gw2   = (const float*)d_in[8];
    const float* gb2   = (const float*)d_in[9];
    const float* hw1   = (const float*)d_in[10];
    const float* hb1   = (const float*)d_in[11];
    const float* hw2   = (const float*)d_in[12];
    const float* hb2   = (const float*)d_in[13];
    const float* finw  = (const float*)d_in[14];
    const float* finb  = (const float*)d_in[15];
    float* out = (float*)d_out;

    float* f1   = symaddr(g_f1);
    float* f2   = symaddr(g_f2);
    float* bufH = symaddr(g_bufH);
    float* bufB = symaddr(g_bufB);
    float* e    = symaddr(g_e);
    float* w1a  = symaddr(g_w1);
    float* w2a  = symaddr(g_w2);
    float* att1 = symaddr(g_att1);
    float* att2 = symaddr(g_att2);
    float* sT1  = symaddr(g_sT1);
    float* sT2  = symaddr(g_sT2);
    float* sbuf = symaddr(g_s);
    float* agg1 = symaddr(g_agg1);
    float* agg2 = symaddr(g_agg2);
    float* s1r  = symaddr(g_s1r);
    float* s2r  = symaddr(g_s2r);
    float* fw1r = symaddr(g_fw1r);
    float* fw2r = symaddr(g_fw2r);
    float* gw1r = symaddr(g_gw1r);
    float* gw2r = symaddr(g_gw2r);
    float* hw1r = symaddr(g_hw1r);
    float* hw2r = symaddr(g_hw2r);

    cudaFuncSetAttribute((const void*)mma2_gemm<true, true, false, true>,
                         cudaFuncAttributeMaxDynamicSharedMemorySize, SMEM_DYN);
    cudaFuncSetAttribute((const void*)mma2_gemm<true, true, false, false>,
                         cudaFuncAttributeMaxDynamicSharedMemorySize, SMEM_DYN);
    cudaFuncSetAttribute((const void*)mma2_gemm<true, true, true, true>,
                         cudaFuncAttributeMaxDynamicSharedMemorySize, SMEM_DYN);
    cudaFuncSetAttribute((const void*)mma2_gemm<false, false, false, false>,
                         cudaFuncAttributeMaxDynamicSharedMemorySize, SMEM_DYN);
    cudaFuncSetAttribute((const void*)mma2_gemm<false, false, false, true>,
                         cudaFuncAttributeMaxDynamicSharedMemorySize, SMEM_DYN);

    // ---- one-time tf32 rounding of raw operands ----
    auto rcopy = [](const float* src, float* dst, long n) {
        int n4 = (int)(n / 4);
        round_copy_kernel<<<(n4 + 255) / 256, 256>>>(src, dst, n4);
    };
    rcopy(sent1, s1r, (long)TOK * EMB);
    rcopy(sent2, s2r, (long)TOK * EMB);
    rcopy(f_w1, fw1r, (long)HID * EMB);
    rcopy(f_w2, fw2r, (long)HID * HID);
    rcopy(gw1,  gw1r, (long)HID * 2 * EMB);
    rcopy(gw2,  gw2r, (long)HID * HID);
    rcopy(hw1,  hw1r, (long)HID * 2 * HID);
    rcopy(hw2,  hw2r, (long)HID * HID);

    // C = act(A @ W^T + b); CVT rounds C for GEMM-feeding outputs
    auto mlp_cvt = [](const float* A, const float* W, const float* b, float* C,
                      int M, int N, int K) {
        dim3 grid(N / BN, M / BM, 1);
        mma2_gemm<true, true, false, true><<<grid, 256, SMEM_DYN>>>(
            A, nullptr, W, b, C, N, K, 0, 0, 0);
    };
    auto mlp_raw = [](const float* A, const float* W, const float* b, float* C,
                      int M, int N, int K) {
        dim3 grid(N / BN, M / BM, 1);
        mma2_gemm<true, true, false, false><<<grid, 256, SMEM_DYN>>>(
            A, nullptr, W, b, C, N, K, 0, 0, 0);
    };
    auto mlp_split = [](const float* att, const float* sent, const float* W,
                        const float* b, float* C, int M, int N) {
        dim3 grid(N / BN, M / BM, 1);
        mma2_gemm<true, true, true, true><<<grid, 256, SMEM_DYN>>>(
            att, sent, W, b, C, N, 2 * EMB, 0, 0, 0);
    };

    // ---- transposes (tf32-rounded) for attention @ sentence products ----
    {
        dim3 tg(EMB / 32, L / 32, NB);
        transpose_kernel<<<tg, dim3(32, 8)>>>(sent1, sT1);
        transpose_kernel<<<tg, dim3(32, 8)>>>(sent2, sT2);
    }

    // ---- Attend: f MLP on both sentences ----
    mlp_cvt(s1r,  fw1r, f_b1, bufH, TOK, HID, EMB);
    mlp_cvt(bufH, fw2r, f_b2, f1,   TOK, HID, HID);
    mlp_cvt(s2r,  fw1r, f_b1, bufH, TOK, HID, EMB);
    mlp_cvt(bufH, fw2r, f_b2, f2,   TOK, HID, HID);

    // e1[b] = f1[b] @ f2[b]^T   (batched NT, 256x256x1024); e NOT rounded
    {
        dim3 grid(L / BN, L / BM, NB);
        mma2_gemm<false, false, false, false><<<grid, 256, SMEM_DYN>>>(
            f1, nullptr, f2, nullptr, e, L, HID,
            (long)L * HID, (long)L * HID, (long)L * L);
    }

    softmax_rows_kernel<<<NB * L, 256>>>(e, w1a);
    softmax_cols_kernel<<<dim3(NB, L / 32), 256>>>(e, w2a);

    // att1[b] = w1a[b] @ sT2[b]^T,  att2[b] = w2a[b] @ sT1[b]^T (rounded out)
    {
        dim3 grid(EMB / BN, L / BM, NB);
        mma2_gemm<false, false, false, true><<<grid, 256, SMEM_DYN>>>(
            w1a, nullptr, sT2, nullptr, att1, EMB, L,
            (long)L * L, (long)EMB * L, (long)L * EMB);
        mma2_gemm<false, false, false, true><<<grid, 256, SMEM_DYN>>>(
            w2a, nullptr, sT1, nullptr, att2, EMB, L,
            (long)L * L, (long)EMB * L, (long)L * EMB);
    }

    // ---- Compare + aggregate-sum, sentence 1 ----
    mlp_split(att1, s1r, gw1r, gb1, bufH, TOK, HID);
    mlp_raw(bufH, gw2r, gb2, bufB, TOK, HID, HID);
    colsum_kernel<<<dim3(NB, HID / 256), 256>>>(bufB, sbuf, 0);

    // ---- Compare + aggregate-sum, sentence 2 ----
    mlp_split(att2, s2r, gw1r, gb1, bufH, TOK, HID);
    mlp_raw(bufH, gw2r, gb2, bufB, TOK, HID, HID);
    colsum_kernel<<<dim3(NB, HID / 256), 256>>>(bufB, sbuf, HID);

    // ---- Aggregate MLP + final linear ----
    mlp_cvt(sbuf, hw1r, hb1, agg1, NB, HID, 2 * HID);
    mlp_raw(agg1, hw2r, hb2, agg2, NB, HID, HID);
    final_kernel<<<NB, 96>>>(agg2, finw, finb, out);
}

// round 17
// speedup vs baseline: 4.2504x; 1.0393x over previous
#include <cuda_runtime.h>
#include <cstdint>

// ---------------- problem constants ----------------
#define NB   128            // batch
#define L    256            // seq len (both sentences)
#define EMB  512
#define HID  1024
#define TOK  (NB * L)       // 32768 tokens per sentence

// ---------------- scratch (device globals; no allocations) ----------------
__device__ __align__(16) float g_f1  [TOK * HID];
__device__ __align__(16) float g_f2  [TOK * HID];
__device__ __align__(16) float g_bufH[TOK * HID];
__device__ __align__(16) float g_bufB[TOK * HID];
__device__ __align__(16) float g_e   [NB * L * L];
__device__ __align__(16) float g_w1  [NB * L * L];   // row softmax [B,L1,L2]
__device__ __align__(16) float g_w2  [NB * L * L];   // col softmax [B,L2,L1]
__device__ __align__(16) float g_att1[NB * L * EMB];
__device__ __align__(16) float g_att2[NB * L * EMB];
__device__ __align__(16) float g_sT1 [NB * EMB * L]; // sent1^T (rounded)
__device__ __align__(16) float g_sT2 [NB * EMB * L]; // sent2^T (rounded)
__device__ __align__(16) float g_s   [NB * 2 * HID]; // [s1 | s2] (rounded)
__device__ __align__(16) float g_agg1[NB * HID];
__device__ __align__(16) float g_agg2[NB * HID];
// tf32-prerounded copies of raw GEMM operands
__device__ __align__(16) float g_s1r [TOK * EMB];
__device__ __align__(16) float g_s2r [TOK * EMB];
__device__ __align__(16) float g_fw1r[HID * EMB];
__device__ __align__(16) float g_fw2r[HID * HID];
__device__ __align__(16) float g_gw1r[HID * 2 * EMB];
__device__ __align__(16) float g_gw2r[HID * HID];
__device__ __align__(16) float g_hw1r[HID * 2 * HID];
__device__ __align__(16) float g_hw2r[HID * HID];

// ---------------- PTX helpers ----------------
__device__ __forceinline__ uint32_t smem_u32(const void* p)
{
    uint32_t a;
    asm("{ .reg .u64 t; cvta.to.shared.u64 t, %1; cvt.u32.u64 %0, t; }"
        : "=r"(a) : "l"(p));
    return a;
}

__device__ __forceinline__ float f2t_f(float x)
{
    unsigned u;
    asm("cvt.rna.tf32.f32 %0, %1;" : "=r"(u) : "f"(x));
    return __uint_as_float(u);
}

__device__ __forceinline__ void cp_async16(uint32_t dst, const void* src)
{
    asm volatile("cp.async.cg.shared.global [%0], [%1], 16;"
                 :: "r"(dst), "l"(src) : "memory");
}
__device__ __forceinline__ void cp_commit()
{
    asm volatile("cp.async.commit_group;" ::: "memory");
}
template<int N>
__device__ __forceinline__ void cp_wait()
{
    asm volatile("cp.async.wait_group %0;" :: "n"(N) : "memory");
}

__device__ __forceinline__ void ldsm4(unsigned* r, uint32_t addr)
{
    asm volatile("ldmatrix.sync.aligned.m8n8.x4.shared.b16 {%0,%1,%2,%3}, [%4];"
                 : "=r"(r[0]), "=r"(r[1]), "=r"(r[2]), "=r"(r[3]) : "r"(addr));
}

__device__ __forceinline__ void mma_tf32(float* c, const unsigned* a, const unsigned* b)
{
    asm volatile(
        "mma.sync.aligned.m16n8k8.row.col.f32.tf32.tf32.f32 "
        "{%0,%1,%2,%3},{%4,%5,%6,%7},{%8,%9},{%0,%1,%2,%3};"
        : "+f"(c[0]), "+f"(c[1]), "+f"(c[2]), "+f"(c[3])
        : "r"(a[0]), "r"(a[1]), "r"(a[2]), "r"(a[3]), "r"(b[0]), "r"(b[1]));
}

// ---------------- tf32 round-copy (one-time operand preprocessing) --------
__global__ void round_copy_kernel(const float* __restrict__ in,
                                  float* __restrict__ out, int n4)
{
    int i = blockIdx.x * 256 + threadIdx.x;
    if (i < n4) {
        float4 v = *(const float4*)(in + 4 * (long)i);
        v.x = f2t_f(v.x); v.y = f2t_f(v.y);
        v.z = f2t_f(v.z); v.w = f2t_f(v.w);
        *(float4*)(out + 4 * (long)i) = v;
    }
}

// ---------------- tf32 mma.sync GEMM, ldmatrix + cp.async ----------------
// C = act(A @ B^T + bias); A:[M,K] row-major, B:[N,K] row-major (NT form).
// ALL operands must already be tf32-rounded in memory (mainloop has no cvt).
// SPLIT: A = concat(A[:,0:512], A2[:,0:512]) along K (fused compare concat).
// CVT: round outputs to tf32 in the epilogue (for GEMM-feeding outputs).
// CTA tile 128x256, 8 warps (2x4) of 64x64. Pipeline stage = 64-wide k-block
// built from TWO of the proven 32-wide sub-tiles ([A32|B32][A32|B32], one
// commit group). 2 stages, R14 loop skeleton => HALF the syncs per k of work.
#define BM 128
#define BN 256
#define SUB_BYTES   ((BM + BN) * 32 * 4)   // 49152 per 32-wide sub-tile
#define STAGE_BYTES (2 * SUB_BYTES)        // 98304 per 64-wide stage
#define NSTAGE 2
#define SMEM_DYN (NSTAGE * STAGE_BYTES + 1024)   // 197632

template<bool BIAS, bool RELU, bool SPLIT, bool CVT>
__global__ void __launch_bounds__(256, 1)
mma2_gemm(const float* __restrict__ A, const float* __restrict__ A2,
          const float* __restrict__ B, const float* __restrict__ bias,
          float* __restrict__ C, int N, int K,
          long sA, long sB, long sC)
{
    extern __shared__ char dsm[];
    char* abase = (char*)(((uintptr_t)dsm + 1023) & ~(uintptr_t)1023);
    const uint32_t smem0 = smem_u32(abase);

    const int tid  = threadIdx.x;
    const int lane = tid & 31;
    const int warp = tid >> 5;
    const int wm   = warp >> 2;          // 0..1  (64-row slice)
    const int wn   = warp & 3;           // 0..3  (64-col slice)
    const int bx = blockIdx.x, by = blockIdx.y, bz = blockIdx.z;

    // global operand bases
    const float* Ab;
    const float* A2b = nullptr;
    if (SPLIT) {
        Ab  = A  + (long)by * BM * EMB;
        A2b = A2 + (long)by * BM * EMB;
    } else {
        Ab = A + bz * sA + (long)by * BM * (long)K;
    }
    const float* Bb = B + bz * sB + (long)bx * BN * (long)K;
    float* Cb = C + bz * sC + (long)by * BM * (long)N + bx * BN;

    // ---- per-lane ldmatrix geometry (byte offsets within a 32-sub-tile) ----
    const int g  = lane >> 3;
    const int lr = lane & 7;
    const uint32_t swz = (uint32_t)lr << 4;
    const uint32_t aRow = (uint32_t)(wm * 64 + ((g & 1) << 3) + lr) * 128
                        + ((uint32_t)(g >> 1) << 4);
    const uint32_t bRow = (uint32_t)(wn * 64 + ((g >> 1) << 3) + lr) * 128
                        + ((uint32_t)(g & 1) << 4);

    // ---- staging: one 64-wide stage = two 32-wide sub-tiles, one group ----
    auto issue_stage = [&](int k0, int s) {
#pragma unroll
        for (int sub = 0; sub < 2; sub++) {
            int ks = k0 + sub * 32;
            uint32_t dstA = smem0 + s * STAGE_BYTES + sub * SUB_BYTES;
            uint32_t dstB = dstA + BM * 32 * 4;
            const float* Asrc;
            long strideA;
            if (SPLIT) {
                Asrc = (ks < EMB) ? (Ab + ks) : (A2b + (ks - EMB));
                strideA = EMB;
            } else {
                Asrc = Ab + ks;
                strideA = K;
            }
#pragma unroll
            for (int it = 0; it < 4; it++) {          // A: 128x32 = 1024 f4
                int id = it * 256 + tid;
                int row = id >> 3, c4 = (id & 7) << 2;
                uint32_t d = dstA + (((uint32_t)row * 128 + ((uint32_t)c4 << 2))
                                     ^ (((uint32_t)row & 7) << 4));
                cp_async16(d, Asrc + (long)row * strideA + c4);
            }
#pragma unroll
            for (int it = 0; it < 8; it++) {          // B: 256x32 = 2048 f4
                int id = it * 256 + tid;
                int row = id >> 3, c4 = (id & 7) << 2;
                uint32_t d = dstB + (((uint32_t)row * 128 + ((uint32_t)c4 << 2))
                                     ^ (((uint32_t)row & 7) << 4));
                cp_async16(d, Bb + (long)row * K + ks + c4);
            }
        }
        cp_commit();
    };

    // ---- accumulators ----
    float acc[4][8][4];
#pragma unroll
    for (int i = 0; i < 4; i++)
#pragma unroll
        for (int j = 0; j < 8; j++)
#pragma unroll
            for (int q = 0; q < 4; q++) acc[i][j][q] = 0.f;

    // ---- compute one 64-wide stage (2 sub-tiles x 4 kt; NO cvt) ----
    auto compute = [&](int s) {
#pragma unroll
        for (int sub = 0; sub < 2; sub++) {
            uint32_t baseA = smem0 + s * STAGE_BYTES + sub * SUB_BYTES;
            uint32_t baseB = baseA + BM * 32 * 4;
#pragma unroll
            for (int kt = 0; kt < 4; kt++) {
                unsigned a[4][4], b[4][4];
#pragma unroll
                for (int mt = 0; mt < 4; mt++)
                    ldsm4(a[mt], baseA + ((aRow + mt * 2048 + kt * 32) ^ swz));
#pragma unroll
                for (int np = 0; np < 4; np++)
                    ldsm4(b[np], baseB + ((bRow + np * 2048 + kt * 32) ^ swz));
#pragma unroll
                for (int mt = 0; mt < 4; mt++)
#pragma unroll
                    for (int np = 0; np < 4; np++) {
                        mma_tf32(acc[mt][2 * np + 0], a[mt], &b[np][0]);
                        mma_tf32(acc[mt][2 * np + 1], a[mt], &b[np][2]);
                    }
            }
        }
    };

    // ---- pipelined mainloop (R14 skeleton, 64-wide stages, 2 buffers) ----
    const int nK = K >> 6;
    issue_stage(0, 0);
    if (nK > 1) issue_stage(64, 1);
    cp_wait<1>();
    __syncthreads();

    for (int i = 0; i < nK; i++) {
        compute(i & 1);
        __syncthreads();
        if (i + 2 < nK) {
            issue_stage((i + 2) << 6, i & 1);
            cp_wait<1>();
        } else {
            cp_wait<0>();
        }
        __syncthreads();
    }

    // ---- epilogue: bias + relu (+ tf32 round) + float2 stores ----
    const int g4 = lane >> 2, t = lane & 3;
#pragma unroll
    for (int j = 0; j < 8; j++) {
        int col = wn * 64 + j * 8 + t * 2;
        float2 bb = make_float2(0.f, 0.f);
        if (BIAS) bb = *(const float2*)(bias + (long)bx * BN + col);
#pragma unroll
        for (int i = 0; i < 4; i++) {
            int row = wm * 64 + i * 16 + g4;
            float2 v0 = make_float2(acc[i][j][0] + bb.x, acc[i][j][1] + bb.y);
            float2 v1 = make_float2(acc[i][j][2] + bb.x, acc[i][j][3] + bb.y);
            if (RELU) {
                v0.x = fmaxf(v0.x, 0.f); v0.y = fmaxf(v0.y, 0.f);
                v1.x = fmaxf(v1.x, 0.f); v1.y = fmaxf(v1.y, 0.f);
            }
            if (CVT) {
                v0.x = f2t_f(v0.x); v0.y = f2t_f(v0.y);
                v1.x = f2t_f(v1.x); v1.y = f2t_f(v1.y);
            }
            *(float2*)(Cb + (long)row * N + col)       = v0;
            *(float2*)(Cb + (long)(row + 8) * N + col) = v1;
        }
    }
}

// ---------------- per-batch transpose: [L,EMB] -> [EMB,L], tf32-rounded ---
__global__ void transpose_kernel(const float* __restrict__ in,
                                 float* __restrict__ out)
{
    __shared__ float t[32][33];
    int b  = blockIdx.z;
    int r0 = blockIdx.y * 32;            // L dim
    int c0 = blockIdx.x * 32;            // EMB dim
    const float* ib = in + (long)b * L * EMB;
    float* ob = out + (long)b * EMB * L;
    int x = threadIdx.x, y = threadIdx.y;
#pragma unroll
    for (int i = 0; i < 32; i += 8)
        t[y + i][x] = ib[(long)(r0 + y + i) * EMB + c0 + x];
    __syncthreads();
#pragma unroll
    for (int i = 0; i < 32; i += 8)
        ob[(long)(c0 + y + i) * L + r0 + x] = f2t_f(t[x][y + i]);
}

// ---------------- softmax over rows, tf32-rounded output ----------------
__global__ void softmax_rows_kernel(const float* __restrict__ e,
                                    float* __restrict__ w)
{
    long row = blockIdx.x;               // b*L + i
    int t = threadIdx.x;                 // j (256 threads)
    float v = e[row * L + t];

    __shared__ float sm[8];
    float m = v;
#pragma unroll
    for (int s = 16; s; s >>= 1) m = fmaxf(m, __shfl_xor_sync(~0u, m, s));
    if ((t & 31) == 0) sm[t >> 5] = m;
    __syncthreads();
    m = sm[0];
#pragma unroll
    for (int k = 1; k < 8; k++) m = fmaxf(m, sm[k]);
    __syncthreads();

    float ex = __expf(v - m);
    float s = ex;
#pragma unroll
    for (int sh = 16; sh; sh >>= 1) s += __shfl_xor_sync(~0u, s, sh);
    if ((t & 31) == 0) sm[t >> 5] = s;
    __syncthreads();
    s = sm[0];
#pragma unroll
    for (int k = 1; k < 8; k++) s += sm[k];

    w[row * L + t] = f2t_f(ex * (1.f / s));
}

// ---------------- softmax over columns, tf32-rounded output ----------------
__global__ void softmax_cols_kernel(const float* __restrict__ e,
                                    float* __restrict__ w2)
{
    int b  = blockIdx.x;
    int j0 = blockIdx.y * 32;
    int tx = threadIdx.x & 31;
    int ty = threadIdx.x >> 5;           // 0..7

    const float* eb = e + (long)b * L * L;
    float vals[32];
    float m = -1e30f;
#pragma unroll
    for (int r = 0; r < 32; r++) {
        float v = eb[(long)(ty + 8 * r) * L + j0 + tx];
        vals[r] = v;
        m = fmaxf(m, v);
    }
    __shared__ float red[8][33];
    red[ty][tx] = m;
    __syncthreads();
    if (ty == 0) {
        float mm = red[0][tx];
#pragma unroll
        for (int t = 1; t < 8; t++) mm = fmaxf(mm, red[t][tx]);
        red[0][tx] = mm;
    }
    __syncthreads();
    m = red[0][tx];
    __syncthreads();

    float s = 0.f;
#pragma unroll
    for (int r = 0; r < 32; r++) { vals[r] = __expf(vals[r] - m); s += vals[r]; }
    red[ty][tx] = s;
    __syncthreads();
    if (ty == 0) {
        float ss = red[0][tx];
#pragma unroll
        for (int t = 1; t < 8; t++) ss += red[t][tx];
        red[0][tx] = ss;
    }
    __syncthreads();
    float inv = 1.f / red[0][tx];

    float* wb = w2 + (long)b * L * L;
#pragma unroll
    for (int r = 0; r < 32; r++)
        wb[(long)(j0 + tx) * L + (ty + 8 * r)] = f2t_f(vals[r] * inv);
}

// ---------------- column sum over seq, tf32-rounded output ----------------
__global__ void colsum_kernel(const float* __restrict__ cmp,
                              float* __restrict__ s, int offset)
{
    int b = blockIdx.x;
    int h = blockIdx.y * 256 + threadIdx.x;
    const float* p = cmp + (long)b * L * HID + h;
    float acc = 0.f;
#pragma unroll 4
    for (int i = 0; i < L; i++) acc += p[(long)i * HID];
    s[(long)b * (2 * HID) + offset + h] = f2t_f(acc);
}

// ---------------- final linear: out[b,o] = agg2[b,:] . fin_w[o,:] + b ------
__global__ void final_kernel(const float* __restrict__ h,
                             const float* __restrict__ w,
                             const float* __restrict__ bias,
                             float* __restrict__ out)
{
    int b = blockIdx.x;
    int o = threadIdx.x >> 5;            // 3 warps
    int lane = threadIdx.x & 31;
    float acc = 0.f;
    for (int k = lane; k < HID; k += 32)
        acc += h[(long)b * HID + k] * w[(long)o * HID + k];
#pragma unroll
    for (int s = 16; s; s >>= 1) acc += __shfl_xor_sync(~0u, acc, s);
    if (lane == 0) out[b * 3 + o] = acc + bias[o];
}

// ---------------- host ----------------
static float* symaddr(const void* sym)
{
    void* p = nullptr;
    cudaGetSymbolAddress(&p, sym);
    return (float*)p;
}

extern "C" void kernel_launch(void* const* d_in, const int* in_sizes, int n_in,
                              void* d_out, int out_size)
{
    (void)in_sizes; (void)n_in; (void)out_size;

    const float* sent1 = (const float*)d_in[0];
    const float* sent2 = (const float*)d_in[1];
    const float* f_w1  = (const float*)d_in[2];
    const float* f_b1  = (const float*)d_in[3];
    const float* f_w2  = (const float*)d_in[4];
    const float* f_b2  = (const float*)d_in[5];
    const float* gw1   = (const float*)d_in[6];
    const float* gb1   = (const float*)d_in[7];
    const float* gw2   = (const float*)d_in[8];
    const float* gb2   = (const float*)d_in[9];
    const float* hw1   = (const float*)d_in[10];
    const float* hb1   = (const float*)d_in[11];
    const float* hw2   = (const float*)d_in[12];
    const float* hb2   = (const float*)d_in[13];
    const float* finw  = (const float*)d_in[14];
    const float* finb  = (const float*)d_in[15];
    float* out = (float*)d_out;

    float* f1   = symaddr(g_f1);
    float* f2   = symaddr(g_f2);
    float* bufH = symaddr(g_bufH);
    float* bufB = symaddr(g_bufB);
    float* e    = symaddr(g_e);
    float* w1a  = symaddr(g_w1);
    float* w2a  = symaddr(g_w2);
    float* att1 = symaddr(g_att1);
    float* att2 = symaddr(g_att2);
    float* sT1  = symaddr(g_sT1);
    float* sT2  = symaddr(g_sT2);
    float* sbuf = symaddr(g_s);
    float* agg1 = symaddr(g_agg1);
    float* agg2 = symaddr(g_agg2);
    float* s1r  = symaddr(g_s1r);
    float* s2r  = symaddr(g_s2r);
    float* fw1r = symaddr(g_fw1r);
    float* fw2r = symaddr(g_fw2r);
    float* gw1r = symaddr(g_gw1r);
    float* gw2r = symaddr(g_gw2r);
    float* hw1r = symaddr(g_hw1r);
    float* hw2r = symaddr(g_hw2r);

    cudaFuncSetAttribute((const void*)mma2_gemm<true, true, false, true>,
                         cudaFuncAttributeMaxDynamicSharedMemorySize, SMEM_DYN);
    cudaFuncSetAttribute((const void*)mma2_gemm<true, true, false, false>,
                         cudaFuncAttributeMaxDynamicSharedMemorySize, SMEM_DYN);
    cudaFuncSetAttribute((const void*)mma2_gemm<true, true, true, true>,
                         cudaFuncAttributeMaxDynamicSharedMemorySize, SMEM_DYN);
    cudaFuncSetAttribute((const void*)mma2_gemm<false, false, false, false>,
                         cudaFuncAttributeMaxDynamicSharedMemorySize, SMEM_DYN);
    cudaFuncSetAttribute((const void*)mma2_gemm<false, false, false, true>,
                         cudaFuncAttributeMaxDynamicSharedMemorySize, SMEM_DYN);

    // ---- one-time tf32 rounding of raw operands ----
    auto rcopy = [](const float* src, float* dst, long n) {
        int n4 = (int)(n / 4);
        round_copy_kernel<<<(n4 + 255) / 256, 256>>>(src, dst, n4);
    };
    rcopy(sent1, s1r, (long)TOK * EMB);
    rcopy(sent2, s2r, (long)TOK * EMB);
    rcopy(f_w1, fw1r, (long)HID * EMB);
    rcopy(f_w2, fw2r, (long)HID * HID);
    rcopy(gw1,  gw1r, (long)HID * 2 * EMB);
    rcopy(gw2,  gw2r, (long)HID * HID);
    rcopy(hw1,  hw1r, (long)HID * 2 * HID);
    rcopy(hw2,  hw2r, (long)HID * HID);

    // C = act(A @ W^T + b); CVT rounds C for GEMM-feeding outputs
    auto mlp_cvt = [](const float* A, const float* W, const float* b, float* C,
                      int M, int N, int K) {
        dim3 grid(N / BN, M / BM, 1);
        mma2_gemm<true, true, false, true><<<grid, 256, SMEM_DYN>>>(
            A, nullptr, W, b, C, N, K, 0, 0, 0);
    };
    auto mlp_raw = [](const float* A, const float* W, const float* b, float* C,
                      int M, int N, int K) {
        dim3 grid(N / BN, M / BM, 1);
        mma2_gemm<true, true, false, false><<<grid, 256, SMEM_DYN>>>(
            A, nullptr, W, b, C, N, K, 0, 0, 0);
    };
    auto mlp_split = [](const float* att, const float* sent, const float* W,
                        const float* b, float* C, int M, int N) {
        dim3 grid(N / BN, M / BM, 1);
        mma2_gemm<true, true, true, true><<<grid, 256, SMEM_DYN>>>(
            att, sent, W, b, C, N, 2 * EMB, 0, 0, 0);
    };

    // ---- transposes (tf32-rounded) for attention @ sentence products ----
    {
        dim3 tg(EMB / 32, L / 32, NB);
        transpose_kernel<<<tg, dim3(32, 8)>>>(sent1, sT1);
        transpose_kernel<<<tg, dim3(32, 8)>>>(sent2, sT2);
    }

    // ---- Attend: f MLP on both sentences ----
    mlp_cvt(s1r,  fw1r, f_b1, bufH, TOK, HID, EMB);
    mlp_cvt(bufH, fw2r, f_b2, f1,   TOK, HID, HID);
    mlp_cvt(s2r,  fw1r, f_b1, bufH, TOK, HID, EMB);
    mlp_cvt(bufH, fw2r, f_b2, f2,   TOK, HID, HID);

    // e1[b] = f1[b] @ f2[b]^T   (batched NT, 256x256x1024); e NOT rounded
    {
        dim3 grid(L / BN, L / BM, NB);
        mma2_gemm<false, false, false, false><<<grid, 256, SMEM_DYN>>>(
            f1, nullptr, f2, nullptr, e, L, HID,
            (long)L * HID, (long)L * HID, (long)L * L);
    }

    softmax_rows_kernel<<<NB * L, 256>>>(e, w1a);
    softmax_cols_kernel<<<dim3(NB, L / 32), 256>>>(e, w2a);

    // att1[b] = w1a[b] @ sT2[b]^T,  att2[b] = w2a[b] @ sT1[b]^T (rounded out)
    {
        dim3 grid(EMB / BN, L / BM, NB);
        mma2_gemm<false, false, false, true><<<grid, 256, SMEM_DYN>>>(
            w1a, nullptr, sT2, nullptr, att1, EMB, L,
            (long)L * L, (long)EMB * L, (long)L * EMB);
        mma2_gemm<false, false, false, true><<<grid, 256, SMEM_DYN>>>(
            w2a, nullptr, sT1, nullptr, att2, EMB, L,
            (long)L * L, (long)EMB * L, (long)L * EMB);
    }

    // ---- Compare + aggregate-sum, sentence 1 ----
    mlp_split(att1, s1r, gw1r, gb1, bufH, TOK, HID);
    mlp_raw(bufH, gw2r, gb2, bufB, TOK, HID, HID);
    colsum_kernel<<<dim3(NB, HID / 256), 256>>>(bufB, sbuf, 0);

    // ---- Compare + aggregate-sum, sentence 2 ----
    mlp_split(att2, s2r, gw1r, gb1, bufH, TOK, HID);
    mlp_raw(bufH, gw2r, gb2, bufB, TOK, HID, HID);
    colsum_kernel<<<dim3(NB, HID / 256), 256>>>(bufB, sbuf, HID);

    // ---- Aggregate MLP + final linear ----
    mlp_cvt(sbuf, hw1r, hb1, agg1, NB, HID, 2 * HID);
    mlp_raw(agg1, hw2r, hb2, agg2, NB, HID, HID);
    final_kernel<<<NB, 96>>>(agg2, finw, finb, out);
}